// round 1
// baseline (speedup 1.0000x reference)
#include <cuda_runtime.h>
#include <math.h>

#define NN_ 768
#define CC_ 768
#define CS_ 384
#define CP_ 128
#define HH_ 16
#define KD_ 48
#define FF_ 1536
#define LL_ 8
#define NC_ (NN_*CC_)          /* 589824 */
#define NNSQ_ 589824LL

// ---------------- scratch (static device globals; no allocation) ----------------
__device__ static float g_pl[LL_*HH_*NN_*NN_];   // 302 MB pair logits [l][h][q][k]
__device__ static float g_lg[HH_*NN_*NN_];       // logits/weights scratch
__device__ static float g_x[NC_];
__device__ static float g_q[NC_], g_k[NC_], g_v[NC_], g_gate[NC_], g_wa[NC_];
__device__ static float g_u[NN_*2*FF_], g_c[NN_*FF_];
__device__ static float g_lnsc[NN_*CS_];
__device__ static float g_cnA[LL_*NN_*CS_], g_cnF[LL_*NN_*CS_];
__device__ static float g_sigA[LL_*NC_], g_addA[LL_*NC_], g_azcA[LL_*NC_];
__device__ static float g_sigF[LL_*NC_], g_addF[LL_*NC_], g_azcF[LL_*NC_];
__device__ static float g_bias[NN_];

// ---------------- reductions ----------------
__device__ __forceinline__ float blockReduce(float v, float* red, bool ismax){
    __syncthreads();
    int lane = threadIdx.x & 31, w = threadIdx.x >> 5, nw = blockDim.x >> 5;
    #pragma unroll
    for (int o = 16; o; o >>= 1){
        float u = __shfl_xor_sync(0xffffffffu, v, o);
        v = ismax ? fmaxf(v, u) : v + u;
    }
    if (lane == 0) red[w] = v;
    __syncthreads();
    if (w == 0){
        v = (lane < nw) ? red[lane] : (ismax ? -1e30f : 0.f);
        #pragma unroll
        for (int o = 16; o; o >>= 1){
            float u = __shfl_xor_sync(0xffffffffu, v, o);
            v = ismax ? fmaxf(v, u) : v + u;
        }
        if (lane == 0) red[0] = v;
    }
    __syncthreads();
    return red[0];
}

// ---------------- generic fp32 GEMM, 64x64x16 tile, 4x4/thread ----------------
// modes: 0 C=acc | 1 C=acc+P1[n] | 2 C=sigmoid(acc+P1[n])
//        3 C=acc*alpha+P1[n]+P2[m*ldc+n] | 4 C[ci]+=P1[ci]*acc
__global__ void gemm_k(int M, int N, int K,
    const float* __restrict__ A, int lda, long long sA,
    const float* __restrict__ B, int ldb, long long sB, int transB,
    float* __restrict__ C, int ldc, long long sC,
    int mode, const float* __restrict__ P1, long long sP1,
    const float* __restrict__ P2, long long sP2, float alpha)
{
    __shared__ float As[16][65];
    __shared__ float Bs[16][64];
    int bz = blockIdx.z;
    A += (long long)bz * sA;
    B += (long long)bz * sB;
    C += (long long)bz * sC;
    const float* P1b = P1 ? P1 + (long long)bz * sP1 : P1;
    const float* P2b = P2 ? P2 + (long long)bz * sP2 : P2;
    int bm = blockIdx.y << 6, bn = blockIdx.x << 6;
    int t = threadIdx.x, tx = t & 15, ty = t >> 4;
    float acc[4][4] = {};
    float ra[4], rb[4];

    // prologue: load tile k0=0 into regs
    #pragma unroll
    for (int i = 0; i < 4; i++){
        int li = t + (i << 8); int ar = li >> 4, ac = li & 15;
        ra[i] = A[(long long)(bm + ar) * lda + ac];
    }
    #pragma unroll
    for (int i = 0; i < 4; i++){
        int li = t + (i << 8); float v = 0.f;
        if (!transB){ int bk = li >> 6, bnn = li & 63; if (bn + bnn < N) v = B[(long long)bk * ldb + bn + bnn]; }
        else        { int bk = li & 15, bnn = li >> 4; if (bn + bnn < N) v = B[(long long)(bn + bnn) * ldb + bk]; }
        rb[i] = v;
    }

    for (int k0 = 0;;){
        #pragma unroll
        for (int i = 0; i < 4; i++){
            int li = t + (i << 8);
            As[li & 15][li >> 4] = ra[i];
        }
        #pragma unroll
        for (int i = 0; i < 4; i++){
            int li = t + (i << 8);
            if (!transB) Bs[li >> 6][li & 63] = rb[i];
            else         Bs[li & 15][li >> 4] = rb[i];
        }
        __syncthreads();
        int k1 = k0 + 16;
        if (k1 < K){
            #pragma unroll
            for (int i = 0; i < 4; i++){
                int li = t + (i << 8); int ar = li >> 4, ac = li & 15;
                ra[i] = A[(long long)(bm + ar) * lda + k1 + ac];
            }
            #pragma unroll
            for (int i = 0; i < 4; i++){
                int li = t + (i << 8); float v = 0.f;
                if (!transB){ int bk = li >> 6, bnn = li & 63; if (bn + bnn < N) v = B[(long long)(k1 + bk) * ldb + bn + bnn]; }
                else        { int bk = li & 15, bnn = li >> 4; if (bn + bnn < N) v = B[(long long)(bn + bnn) * ldb + k1 + bk]; }
                rb[i] = v;
            }
        }
        #pragma unroll
        for (int kk = 0; kk < 16; kk++){
            float av[4], bv[4];
            #pragma unroll
            for (int i = 0; i < 4; i++) av[i] = As[kk][(ty << 2) + i];
            #pragma unroll
            for (int j = 0; j < 4; j++) bv[j] = Bs[kk][(tx << 2) + j];
            #pragma unroll
            for (int i = 0; i < 4; i++)
                #pragma unroll
                for (int j = 0; j < 4; j++)
                    acc[i][j] += av[i] * bv[j];
        }
        k0 = k1;
        if (k0 >= K) break;
        __syncthreads();
    }

    #pragma unroll
    for (int i = 0; i < 4; i++){
        int m = bm + (ty << 2) + i;
        #pragma unroll
        for (int j = 0; j < 4; j++){
            int n = bn + (tx << 2) + j;
            if (n >= N) continue;
            long long ci = (long long)m * ldc + n;
            float r = acc[i][j];
            if (mode == 0)      C[ci] = r;
            else if (mode == 1) C[ci] = r + P1b[n];
            else if (mode == 2) C[ci] = 1.f / (1.f + expf(-(r + P1b[n])));
            else if (mode == 3) C[ci] = r * alpha + P1b[n] + P2b[(long long)m * ldc + n];
            else                C[ci] = C[ci] + P1b[ci] * r;
        }
    }
}

// ---------------- fused pair LN + pl GEMM ----------------
// per block: 64 (q,k) rows, one super-block (grid.z). LN over 128 ch, then
// [64x128] @ [128x64] -> scatter to g_pl[(nsb*64 + s*16+h)][row]
__global__ void pair_k(const float* __restrict__ pc, const float* __restrict__ scale,
                       const float* __restrict__ pw)
{
    extern __shared__ float sm[];
    float* spc = sm;                  // 64 rows x 129 (padded)
    float* spw = sm + 64 * 129;       // 128 x 64
    float* ssc = spw + 8192;          // 128
    int nsb = blockIdx.z;
    int t = threadIdx.x;
    long long row0 = (long long)blockIdx.x * 64;

    for (int i = t; i < 8192; i += 256) spw[i] = pw[nsb * 8192 + i];
    if (t < 128) ssc[t] = scale[t];
    for (int i = t; i < 64 * 128; i += 256){
        int r = i >> 7, c = i & 127;
        spc[r * 129 + c] = pc[(row0 + r) * 128 + c];
    }
    __syncthreads();

    int w = t >> 5, lane = t & 31;
    for (int rr = 0; rr < 8; rr++){
        int r = w * 8 + rr;
        float* pr = spc + r * 129;
        float x0 = pr[lane], x1 = pr[lane + 32], x2 = pr[lane + 64], x3 = pr[lane + 96];
        float s = x0 + x1 + x2 + x3;
        #pragma unroll
        for (int o = 16; o; o >>= 1) s += __shfl_xor_sync(0xffffffffu, s, o);
        float m = s * (1.f / 128.f);
        x0 -= m; x1 -= m; x2 -= m; x3 -= m;
        float vq = x0 * x0 + x1 * x1 + x2 * x2 + x3 * x3;
        #pragma unroll
        for (int o = 16; o; o >>= 1) vq += __shfl_xor_sync(0xffffffffu, vq, o);
        float rstd = rsqrtf(vq * (1.f / 128.f) + 1e-5f);
        pr[lane]      = x0 * rstd * ssc[lane];
        pr[lane + 32] = x1 * rstd * ssc[lane + 32];
        pr[lane + 64] = x2 * rstd * ssc[lane + 64];
        pr[lane + 96] = x3 * rstd * ssc[lane + 96];
    }
    __syncthreads();

    int tx = t & 15, ty = t >> 4;
    float acc[4][4] = {};
    for (int c = 0; c < 128; c++){
        float av[4], bv[4];
        #pragma unroll
        for (int i = 0; i < 4; i++) av[i] = spc[(4 * ty + i) * 129 + c];
        #pragma unroll
        for (int j = 0; j < 4; j++) bv[j] = spw[c * 64 + 4 * tx + j];
        #pragma unroll
        for (int i = 0; i < 4; i++)
            #pragma unroll
            for (int j = 0; j < 4; j++)
                acc[i][j] += av[i] * bv[j];
    }
    __syncthreads();
    float* sout = spw;   // reuse (4096 floats)
    #pragma unroll
    for (int i = 0; i < 4; i++)
        #pragma unroll
        for (int j = 0; j < 4; j++)
            sout[(4 * tx + j) * 64 + 4 * ty + i] = acc[i][j];
    __syncthreads();
    for (int i = t; i < 4096; i += 256){
        int j = i >> 6, m = i & 63;
        g_pl[((long long)(nsb * 64 + j)) * NNSQ_ + row0 + m] = sout[i];
    }
}

// ---------------- small kernels ----------------
__global__ void bias_k(const float* __restrict__ mask){
    int i = blockIdx.x * 256 + threadIdx.x;
    if (i < NN_) g_bias[i] = 1e9f * (mask[i] - 1.f);
}

__global__ void ln384_k(const float* __restrict__ in){
    int r = blockIdx.x, t = threadIdx.x;   // 128 threads
    __shared__ float red[32];
    const float* p = in + (long long)r * CS_;
    float v0 = p[t], v1 = p[t + 128], v2 = p[t + 256];
    float s = blockReduce(v0 + v1 + v2, red, false);
    float m = s * (1.f / 384.f);
    float d0 = v0 - m, d1 = v1 - m, d2 = v2 - m;
    float q = blockReduce(d0 * d0 + d1 * d1 + d2 * d2, red, false);
    float rstd = rsqrtf(q * (1.f / 384.f) + 1e-5f);
    float* o = g_lnsc + (long long)r * CS_;
    o[t] = d0 * rstd; o[t + 128] = d1 * rstd; o[t + 256] = d2 * rstd;
}

__global__ void cn_k(const float* __restrict__ aln, const float* __restrict__ fln){
    int i = blockIdx.x * 256 + threadIdx.x;
    if (i >= LL_ * NN_ * CS_) return;
    int l = i / (NN_ * CS_);
    int rem = i % (NN_ * CS_);
    int c = rem % CS_;
    float b = g_lnsc[rem];
    g_cnA[i] = b * aln[l * CS_ + c];
    g_cnF[i] = b * fln[l * CS_ + c];
}

__global__ void modulate_k(const float* __restrict__ a, const float* __restrict__ sig,
                           const float* __restrict__ add, float* __restrict__ xo){
    int r = blockIdx.x, t = threadIdx.x;   // 256 threads
    __shared__ float red[32];
    const float* ar = a + (long long)r * 768;
    float v0 = ar[t], v1 = ar[t + 256], v2 = ar[t + 512];
    float s = blockReduce(v0 + v1 + v2, red, false);
    float m = s * (1.f / 768.f);
    float d0 = v0 - m, d1 = v1 - m, d2 = v2 - m;
    float q = blockReduce(d0 * d0 + d1 * d1 + d2 * d2, red, false);
    float rstd = rsqrtf(q * (1.f / 768.f) + 1e-5f);
    long long o = (long long)r * 768;
    xo[o + t]       = sig[o + t]       * (d0 * rstd) + add[o + t];
    xo[o + t + 256] = sig[o + t + 256] * (d1 * rstd) + add[o + t + 256];
    xo[o + t + 512] = sig[o + t + 512] * (d2 * rstd) + add[o + t + 512];
}

__global__ void softmax_k(){
    long long r = blockIdx.x;
    float* p = g_lg + r * NN_;
    int t = threadIdx.x;
    __shared__ float red[32];
    float v0 = p[t], v1 = p[t + 256], v2 = p[t + 512];
    float mx = blockReduce(fmaxf(v0, fmaxf(v1, v2)), red, true);
    float e0 = expf(v0 - mx), e1 = expf(v1 - mx), e2 = expf(v2 - mx);
    float s = blockReduce(e0 + e1 + e2, red, false);
    float inv = 1.f / s;
    p[t] = e0 * inv; p[t + 256] = e1 * inv; p[t + 512] = e2 * inv;
}

__global__ void gatemul_k(){
    int i = blockIdx.x * 256 + threadIdx.x;
    if (i < NC_) g_wa[i] *= g_gate[i];
}

__global__ void glu_k(){
    int i = blockIdx.x * 256 + threadIdx.x;
    if (i >= NN_ * FF_) return;
    int n = i / FF_, f = i % FF_;
    float u1 = g_u[(long long)n * 2 * FF_ + f];
    float u2 = g_u[(long long)n * 2 * FF_ + FF_ + f];
    g_c[i] = (u1 / (1.f + expf(-u1))) * u2;
}

// ---------------- host ----------------
static inline void gemm(int M, int N, int K,
    const float* A, int lda, long long sA,
    const float* B, int ldb, long long sB, int tB,
    float* C, int ldc, long long sC,
    int mode, const float* P1, long long sP1,
    const float* P2, long long sP2, float alpha, int batch)
{
    dim3 gr((N + 63) / 64, M / 64, batch);
    gemm_k<<<gr, 256>>>(M, N, K, A, lda, sA, B, ldb, sB, tB, C, ldc, sC,
                        mode, P1, sP1, P2, sP2, alpha);
}

extern "C" void kernel_launch(void* const* d_in, const int* in_sizes, int n_in,
                              void* d_out, int out_size)
{
    const float* act         = (const float*)d_in[0];
    const float* mask        = (const float*)d_in[1];
    const float* single_cond = (const float*)d_in[2];
    const float* pair_cond   = (const float*)d_in[3];
    const float* attn_cln    = (const float*)d_in[4];
    const float* attn_cs_w   = (const float*)d_in[5];
    const float* attn_cs_b   = (const float*)d_in[6];
    const float* attn_cb_w   = (const float*)d_in[7];
    const float* q_w         = (const float*)d_in[8];
    const float* q_b         = (const float*)d_in[9];
    const float* k_w         = (const float*)d_in[10];
    const float* v_w         = (const float*)d_in[11];
    const float* gate_w      = (const float*)d_in[12];
    const float* gate_b      = (const float*)d_in[13];
    const float* out_w       = (const float*)d_in[14];
    const float* attn_azc_w  = (const float*)d_in[15];
    const float* attn_azc_b  = (const float*)d_in[16];
    const float* ffw_cln     = (const float*)d_in[17];
    const float* ffw_cs_w    = (const float*)d_in[18];
    const float* ffw_cs_b    = (const float*)d_in[19];
    const float* ffw_cb_w    = (const float*)d_in[20];
    const float* t1_w        = (const float*)d_in[21];
    const float* t2_w        = (const float*)d_in[22];
    const float* ffw_azc_w   = (const float*)d_in[23];
    const float* ffw_azc_b   = (const float*)d_in[24];
    const float* pair_lns    = (const float*)d_in[25];
    const float* pair_w      = (const float*)d_in[26];
    float* a = (float*)d_out;

    float *pl, *lg, *x, *qb, *kb, *vb, *gb, *wab, *ub, *cbb;
    float *cnA, *cnF, *sigA, *addA, *azcA, *sigF, *addF, *azcF, *bv;
    cudaGetSymbolAddress((void**)&pl,   g_pl);
    cudaGetSymbolAddress((void**)&lg,   g_lg);
    cudaGetSymbolAddress((void**)&x,    g_x);
    cudaGetSymbolAddress((void**)&qb,   g_q);
    cudaGetSymbolAddress((void**)&kb,   g_k);
    cudaGetSymbolAddress((void**)&vb,   g_v);
    cudaGetSymbolAddress((void**)&gb,   g_gate);
    cudaGetSymbolAddress((void**)&wab,  g_wa);
    cudaGetSymbolAddress((void**)&ub,   g_u);
    cudaGetSymbolAddress((void**)&cbb,  g_c);
    cudaGetSymbolAddress((void**)&cnA,  g_cnA);
    cudaGetSymbolAddress((void**)&cnF,  g_cnF);
    cudaGetSymbolAddress((void**)&sigA, g_sigA);
    cudaGetSymbolAddress((void**)&addA, g_addA);
    cudaGetSymbolAddress((void**)&azcA, g_azcA);
    cudaGetSymbolAddress((void**)&sigF, g_sigF);
    cudaGetSymbolAddress((void**)&addF, g_addF);
    cudaGetSymbolAddress((void**)&azcF, g_azcF);
    cudaGetSymbolAddress((void**)&bv,   g_bias);

    // a = act
    cudaMemcpyAsync(a, act, (size_t)NC_ * sizeof(float), cudaMemcpyDeviceToDevice);

    bias_k<<<3, 256>>>(mask);
    ln384_k<<<NN_, 128>>>(single_cond);
    cn_k<<<(LL_ * NN_ * CS_ + 255) / 256, 256>>>(attn_cln, ffw_cln);

    // fused pair LN + pair-logit GEMM for all 8 layers
    cudaFuncSetAttribute(pair_k, cudaFuncAttributeMaxDynamicSharedMemorySize, 67584);
    pair_k<<<dim3(9216, 1, 2), 256, 66304>>>(pair_cond, pair_lns, pair_w);

    // precompute all layer-constant conditioning (batched over 8 layers)
    long long sNCS = (long long)NN_ * CS_;
    long long sWc  = (long long)CS_ * CC_;
    long long sNC  = (long long)NC_;
    gemm(768, 768, 384, cnA, 384, sNCS, attn_cs_w, 768, sWc, 0, sigA, 768, sNC, 2, attn_cs_b, 768, 0, 0, 0.f, 8);
    gemm(768, 768, 384, cnA, 384, sNCS, attn_cb_w, 768, sWc, 0, addA, 768, sNC, 0, 0, 0, 0, 0, 0.f, 8);
    gemm(768, 768, 384, single_cond, 384, 0, attn_azc_w, 768, sWc, 0, azcA, 768, sNC, 2, attn_azc_b, 768, 0, 0, 0.f, 8);
    gemm(768, 768, 384, cnF, 384, sNCS, ffw_cs_w, 768, sWc, 0, sigF, 768, sNC, 2, ffw_cs_b, 768, 0, 0, 0.f, 8);
    gemm(768, 768, 384, cnF, 384, sNCS, ffw_cb_w, 768, sWc, 0, addF, 768, sNC, 0, 0, 0, 0, 0, 0.f, 8);
    gemm(768, 768, 384, single_cond, 384, 0, ffw_azc_w, 768, sWc, 0, azcF, 768, sNC, 2, ffw_azc_b, 768, 0, 0, 0.f, 8);

    float al = 1.f / sqrtf(48.f);
    for (int l = 0; l < 8; l++){
        long long oNC = (long long)l * NC_;
        // attention
        modulate_k<<<768, 256>>>(a, sigA + oNC, addA + oNC, x);
        gemm(768, 768, 768, x, 768, 0, q_w + oNC, 768, 0, 0, qb, 768, 0, 1, q_b + l * 768, 0, 0, 0, 0.f, 1);
        gemm(768, 768, 768, x, 768, 0, k_w + oNC, 768, 0, 0, kb, 768, 0, 0, 0, 0, 0, 0, 0.f, 1);
        gemm(768, 768, 768, x, 768, 0, v_w + oNC, 768, 0, 0, vb, 768, 0, 0, 0, 0, 0, 0, 0.f, 1);
        gemm(768, 768, 768, x, 768, 0, gate_w + oNC, 768, 0, 0, gb, 768, 0, 2, gate_b + l * 768, 0, 0, 0, 0.f, 1);
        // scores: logits[h,q,k] = alpha * q_h @ k_h^T + bias[k] + pl[l,h,q,k]
        gemm(768, 768, 48, qb, 768, 48, kb, 768, 48, 1, lg, 768, NNSQ_, 3,
             bv, 0, pl + (long long)l * HH_ * NNSQ_, NNSQ_, al, 16);
        softmax_k<<<HH_ * NN_, 256>>>();
        // wa[q, h*48+d] = wts_h @ v_h
        gemm(768, 48, 768, lg, 768, NNSQ_, vb, 768, 48, 0, wab, 768, 48, 0, 0, 0, 0, 0, 0.f, 16);
        gatemul_k<<<(NC_ + 255) / 256, 256>>>();
        gemm(768, 768, 768, wab, 768, 0, out_w + oNC, 768, 0, 0, a, 768, 0, 4, azcA + oNC, 0, 0, 0, 0.f, 1);
        // FFN
        modulate_k<<<768, 256>>>(a, sigF + oNC, addF + oNC, x);
        gemm(768, 3072, 768, x, 768, 0, t1_w + (long long)l * 768 * 3072, 3072, 0, 0, ub, 3072, 0, 0, 0, 0, 0, 0, 0.f, 1);
        glu_k<<<(NN_ * FF_ + 255) / 256, 256>>>();
        gemm(768, 768, 1536, cbb, 1536, 0, t2_w + (long long)l * 1536 * 768, 768, 0, 0, a, 768, 0, 4, azcF + oNC, 0, 0, 0, 0.f, 1);
    }
    (void)in_sizes; (void)n_in; (void)out_size;
}

// round 2
// speedup vs baseline: 1.6502x; 1.6502x over previous
#include <cuda_runtime.h>
#include <math.h>

#define NN_ 768
#define CC_ 768
#define CS_ 384
#define CP_ 128
#define HH_ 16
#define KD_ 48
#define FF_ 1536
#define LL_ 8
#define NC_ (NN_*CC_)
#define NNSQ_ 589824LL

// ---------------- scratch ----------------
__device__ static float g_pl[LL_*HH_*NN_*NN_];
__device__ static float g_lg[HH_*NN_*NN_];
__device__ static float g_x[NC_];
__device__ static float g_q[NC_], g_k[NC_], g_v[NC_], g_gate[NC_], g_wa[NC_];
__device__ static float g_u[NN_*2*FF_], g_c[NN_*FF_];
__device__ static float g_lnsc[NN_*CS_];
__device__ static float g_cnA[LL_*NN_*CS_], g_cnF[LL_*NN_*CS_];
__device__ static float g_sigA[LL_*NC_], g_addA[LL_*NC_], g_azcA[LL_*NC_];
__device__ static float g_sigF[LL_*NC_], g_addF[LL_*NC_], g_azcF[LL_*NC_];
__device__ static float g_bias[NN_];

// ---------------- tf32 mma helpers ----------------
__device__ __forceinline__ unsigned f2tf(float x){
    unsigned r; asm("cvt.rna.tf32.f32 %0, %1;" : "=r"(r) : "f"(x)); return r;
}
__device__ __forceinline__ void mma_tf32(float* c, const unsigned* a, unsigned b0, unsigned b1){
    asm volatile("mma.sync.aligned.m16n8k8.row.col.f32.tf32.tf32.f32 "
        "{%0,%1,%2,%3}, {%4,%5,%6,%7}, {%8,%9}, {%0,%1,%2,%3};\n"
        : "+f"(c[0]),"+f"(c[1]),"+f"(c[2]),"+f"(c[3])
        : "r"(a[0]),"r"(a[1]),"r"(a[2]),"r"(a[3]),"r"(b0),"r"(b1));
}

// ---------------- reductions ----------------
__device__ __forceinline__ float blockReduce(float v, float* red, bool ismax){
    __syncthreads();
    int lane = threadIdx.x & 31, w = threadIdx.x >> 5, nw = blockDim.x >> 5;
    #pragma unroll
    for (int o = 16; o; o >>= 1){
        float u = __shfl_xor_sync(0xffffffffu, v, o);
        v = ismax ? fmaxf(v, u) : v + u;
    }
    if (lane == 0) red[w] = v;
    __syncthreads();
    if (w == 0){
        v = (lane < nw) ? red[lane] : (ismax ? -1e30f : 0.f);
        #pragma unroll
        for (int o = 16; o; o >>= 1){
            float u = __shfl_xor_sync(0xffffffffu, v, o);
            v = ismax ? fmaxf(v, u) : v + u;
        }
        if (lane == 0) red[0] = v;
    }
    __syncthreads();
    return red[0];
}

// ---------------- epilogue ----------------
__device__ __forceinline__ void epi(float* C, int ldc, int mode,
    const float* P1, const float* P2, float alpha, int m, int n, int N, float r)
{
    if (n >= N) return;
    long long ci = (long long)m * ldc + n;
    if (mode == 0)      C[ci] = r;
    else if (mode == 1) C[ci] = r + P1[n];
    else if (mode == 2) C[ci] = 1.f / (1.f + expf(-(r + P1[n])));
    else if (mode == 3) C[ci] = r * alpha + P1[n] + P2[ci];
    else                C[ci] = C[ci] + P1[ci] * r;
}

// ---------------- tf32 tensor-core GEMM: 64x64 tile, BK=32, 256 threads ----------------
// A row-major [M,K]; B: transB=0 -> [K,N], transB=1 -> [N,K]. M multiple of 64.
__global__ void gemm_tc(int M, int N, int K,
    const float* __restrict__ A, int lda, long long sA,
    const float* __restrict__ B, int ldb, long long sB, int transB,
    float* __restrict__ C, int ldc, long long sC,
    int mode, const float* __restrict__ P1, long long sP1,
    const float* __restrict__ P2, long long sP2, float alpha)
{
    __shared__ unsigned As[64 * 36];   // [m][k], stride 36
    __shared__ unsigned Bs[32 * 72];   // [k][n], stride 72
    int bz = blockIdx.z;
    A += (long long)bz * sA;
    B += (long long)bz * sB;
    C += (long long)bz * sC;
    const float* P1b = P1 ? P1 + (long long)bz * sP1 : P1;
    const float* P2b = P2 ? P2 + (long long)bz * sP2 : P2;

    int bm = blockIdx.y << 6, bn = blockIdx.x << 6;
    int t = threadIdx.x, lane = t & 31, w = t >> 5;
    int wm = w & 1, wn = w >> 1;      // warp tile: 32(m) x 16(n)

    // load index precompute
    int a_c = (t & 7) << 2;           // k
    int a_r = t >> 3;                 // 0..31, rows a_r, a_r+32
    int b_c = (t & 15) << 2;          // n (transB=0)
    int b_r = t >> 4;                 // 0..15, k rows b_r, b_r+16
    int bt_c = (t & 7) << 2;          // k (transB=1)
    int bt_r = t >> 3;                // 0..31, n rows bt_r, bt_r+32

    float4 ra[2], rb[2];
    float acc[2][2][4];
    #pragma unroll
    for (int i = 0; i < 2; i++)
        #pragma unroll
        for (int j = 0; j < 2; j++)
            #pragma unroll
            for (int q = 0; q < 4; q++) acc[i][j][q] = 0.f;

    const float4 z4 = make_float4(0.f,0.f,0.f,0.f);

    // prologue load k0=0
    #pragma unroll
    for (int i = 0; i < 2; i++){
        int row = bm + a_r + 32*i;
        ra[i] = (a_c < K) ? *(const float4*)&A[(long long)row * lda + a_c] : z4;
    }
    if (!transB){
        #pragma unroll
        for (int i = 0; i < 2; i++){
            int kr = b_r + 16*i; int n = bn + b_c;
            rb[i] = (kr < K && n < N) ? *(const float4*)&B[(long long)kr * ldb + n] : z4;
        }
    } else {
        #pragma unroll
        for (int i = 0; i < 2; i++){
            int nr = bn + bt_r + 32*i;
            rb[i] = (bt_c < K && nr < N) ? *(const float4*)&B[(long long)nr * ldb + bt_c] : z4;
        }
    }

    for (int k0 = 0;;){
        // STS (convert to tf32)
        #pragma unroll
        for (int i = 0; i < 2; i++){
            uint4 u; u.x=f2tf(ra[i].x); u.y=f2tf(ra[i].y); u.z=f2tf(ra[i].z); u.w=f2tf(ra[i].w);
            *(uint4*)&As[(a_r + 32*i)*36 + a_c] = u;
        }
        if (!transB){
            #pragma unroll
            for (int i = 0; i < 2; i++){
                uint4 u; u.x=f2tf(rb[i].x); u.y=f2tf(rb[i].y); u.z=f2tf(rb[i].z); u.w=f2tf(rb[i].w);
                *(uint4*)&Bs[(b_r + 16*i)*72 + b_c] = u;
            }
        } else {
            #pragma unroll
            for (int i = 0; i < 2; i++){
                int nr = bt_r + 32*i;
                Bs[(bt_c+0)*72 + nr] = f2tf(rb[i].x);
                Bs[(bt_c+1)*72 + nr] = f2tf(rb[i].y);
                Bs[(bt_c+2)*72 + nr] = f2tf(rb[i].z);
                Bs[(bt_c+3)*72 + nr] = f2tf(rb[i].w);
            }
        }
        __syncthreads();

        int k1 = k0 + 32;
        if (k1 < K){
            #pragma unroll
            for (int i = 0; i < 2; i++){
                int row = bm + a_r + 32*i;
                ra[i] = (k1 + a_c < K) ? *(const float4*)&A[(long long)row * lda + k1 + a_c] : z4;
            }
            if (!transB){
                #pragma unroll
                for (int i = 0; i < 2; i++){
                    int kr = k1 + b_r + 16*i; int n = bn + b_c;
                    rb[i] = (kr < K && n < N) ? *(const float4*)&B[(long long)kr * ldb + n] : z4;
                }
            } else {
                #pragma unroll
                for (int i = 0; i < 2; i++){
                    int nr = bn + bt_r + 32*i;
                    rb[i] = (k1 + bt_c < K && nr < N) ? *(const float4*)&B[(long long)nr * ldb + k1 + bt_c] : z4;
                }
            }
        }

        // compute: 4 k8 steps
        #pragma unroll
        for (int k8 = 0; k8 < 32; k8 += 8){
            unsigned af[2][4], bf[2][2];
            #pragma unroll
            for (int mt = 0; mt < 2; mt++){
                int base = (wm*32 + mt*16 + (lane>>2))*36 + k8 + (lane&3);
                af[mt][0] = As[base];
                af[mt][1] = As[base + 8*36];
                af[mt][2] = As[base + 4];
                af[mt][3] = As[base + 8*36 + 4];
            }
            #pragma unroll
            for (int nt = 0; nt < 2; nt++){
                int bi = (k8 + (lane&3))*72 + wn*16 + nt*8 + (lane>>2);
                bf[nt][0] = Bs[bi];
                bf[nt][1] = Bs[bi + 4*72];
            }
            #pragma unroll
            for (int mt = 0; mt < 2; mt++)
                #pragma unroll
                for (int nt = 0; nt < 2; nt++)
                    mma_tf32(acc[mt][nt], af[mt], bf[nt][0], bf[nt][1]);
        }
        k0 = k1;
        if (k0 >= K) break;
        __syncthreads();
    }

    // epilogue
    #pragma unroll
    for (int mt = 0; mt < 2; mt++){
        int r0 = bm + wm*32 + mt*16 + (lane>>2);
        #pragma unroll
        for (int nt = 0; nt < 2; nt++){
            int c0 = bn + wn*16 + nt*8 + 2*(lane&3);
            epi(C, ldc, mode, P1b, P2b, alpha, r0,   c0,   N, acc[mt][nt][0]);
            epi(C, ldc, mode, P1b, P2b, alpha, r0,   c0+1, N, acc[mt][nt][1]);
            epi(C, ldc, mode, P1b, P2b, alpha, r0+8, c0,   N, acc[mt][nt][2]);
            epi(C, ldc, mode, P1b, P2b, alpha, r0+8, c0+1, N, acc[mt][nt][3]);
        }
    }
}

// ---------------- fused pair LN + pl GEMM (tf32 mma) ----------------
__global__ void pair_k(const float* __restrict__ pc, const float* __restrict__ scale,
                       const float* __restrict__ pw)
{
    extern __shared__ unsigned sm[];
    unsigned* spc = sm;                    // 64 x 132 (tf32 after LN)
    unsigned* spw = sm + 64*132;           // 128 x 72 (tf32)
    float*    ssc = (float*)(sm + 64*132 + 128*72);  // 128
    int nsb = blockIdx.z;
    int t = threadIdx.x, lane = t & 31, w = t >> 5;
    long long row0 = (long long)blockIdx.x * 64;

    for (int i = t; i < 128*64; i += 256){
        int c = i >> 6, n = i & 63;
        spw[c*72 + n] = f2tf(pw[nsb*8192 + i]);
    }
    if (t < 128) ssc[t] = scale[t];
    for (int i = t; i < 64*128; i += 256){
        int r = i >> 7, c = i & 127;
        spc[r*132 + c] = __float_as_uint(pc[(row0 + r)*128 + c]);
    }
    __syncthreads();

    // LN per row (8 warps, 8 rows each)
    for (int rr = 0; rr < 8; rr++){
        int r = w*8 + rr;
        unsigned* pr = spc + r*132;
        float x0 = __uint_as_float(pr[lane]);
        float x1 = __uint_as_float(pr[lane+32]);
        float x2 = __uint_as_float(pr[lane+64]);
        float x3 = __uint_as_float(pr[lane+96]);
        float s = x0+x1+x2+x3;
        #pragma unroll
        for (int o = 16; o; o >>= 1) s += __shfl_xor_sync(0xffffffffu, s, o);
        float m = s * (1.f/128.f);
        x0 -= m; x1 -= m; x2 -= m; x3 -= m;
        float vq = x0*x0+x1*x1+x2*x2+x3*x3;
        #pragma unroll
        for (int o = 16; o; o >>= 1) vq += __shfl_xor_sync(0xffffffffu, vq, o);
        float rstd = rsqrtf(vq * (1.f/128.f) + 1e-5f);
        pr[lane]    = f2tf(x0*rstd*ssc[lane]);
        pr[lane+32] = f2tf(x1*rstd*ssc[lane+32]);
        pr[lane+64] = f2tf(x2*rstd*ssc[lane+64]);
        pr[lane+96] = f2tf(x3*rstd*ssc[lane+96]);
    }
    __syncthreads();

    // mma: [64x128]@[128x64] ; 8 warps: wm=w&3 (m-tile 16), wn=w>>2 (n half 32 = 4 n-tiles)
    int wm = w & 3, wn = w >> 2;
    float acc[4][4];
    #pragma unroll
    for (int i = 0; i < 4; i++)
        #pragma unroll
        for (int q = 0; q < 4; q++) acc[i][q] = 0.f;

    #pragma unroll 4
    for (int k8 = 0; k8 < 128; k8 += 8){
        unsigned af[4];
        int base = (wm*16 + (lane>>2))*132 + k8 + (lane&3);
        af[0] = spc[base];
        af[1] = spc[base + 8*132];
        af[2] = spc[base + 4];
        af[3] = spc[base + 8*132 + 4];
        #pragma unroll
        for (int nt = 0; nt < 4; nt++){
            int bi = (k8 + (lane&3))*72 + wn*32 + nt*8 + (lane>>2);
            mma_tf32(acc[nt], af, spw[bi], spw[bi + 4*72]);
        }
    }
    __syncthreads();

    float* sout = (float*)spw;  // 64 x 68
    int r = wm*16 + (lane>>2);
    #pragma unroll
    for (int nt = 0; nt < 4; nt++){
        int c = wn*32 + nt*8 + 2*(lane&3);
        sout[(c  )*68 + r    ] = acc[nt][0];
        sout[(c+1)*68 + r    ] = acc[nt][1];
        sout[(c  )*68 + r + 8] = acc[nt][2];
        sout[(c+1)*68 + r + 8] = acc[nt][3];
    }
    __syncthreads();
    for (int i = t; i < 4096; i += 256){
        int col = i >> 6, m = i & 63;
        g_pl[((long long)(nsb*64 + col))*NNSQ_ + row0 + m] = sout[col*68 + m];
    }
}

// ---------------- small kernels ----------------
__global__ void bias_k(const float* __restrict__ mask){
    int i = blockIdx.x * 256 + threadIdx.x;
    if (i < NN_) g_bias[i] = 1e9f * (mask[i] - 1.f);
}

__global__ void ln384_k(const float* __restrict__ in){
    int r = blockIdx.x, t = threadIdx.x;
    __shared__ float red[32];
    const float* p = in + (long long)r * CS_;
    float v0 = p[t], v1 = p[t+128], v2 = p[t+256];
    float s = blockReduce(v0+v1+v2, red, false);
    float m = s * (1.f/384.f);
    float d0 = v0-m, d1 = v1-m, d2 = v2-m;
    float q = blockReduce(d0*d0+d1*d1+d2*d2, red, false);
    float rstd = rsqrtf(q * (1.f/384.f) + 1e-5f);
    float* o = g_lnsc + (long long)r * CS_;
    o[t] = d0*rstd; o[t+128] = d1*rstd; o[t+256] = d2*rstd;
}

__global__ void cn_k(const float* __restrict__ aln, const float* __restrict__ fln){
    int i = blockIdx.x * 256 + threadIdx.x;
    if (i >= LL_*NN_*CS_) return;
    int l = i / (NN_*CS_);
    int rem = i % (NN_*CS_);
    int c = rem % CS_;
    float b = g_lnsc[rem];
    g_cnA[i] = b * aln[l*CS_ + c];
    g_cnF[i] = b * fln[l*CS_ + c];
}

__global__ void modulate_k(const float* __restrict__ a, const float* __restrict__ sig,
                           const float* __restrict__ add, float* __restrict__ xo){
    int r = blockIdx.x, t = threadIdx.x;
    __shared__ float red[32];
    const float* ar = a + (long long)r * 768;
    float v0 = ar[t], v1 = ar[t+256], v2 = ar[t+512];
    float s = blockReduce(v0+v1+v2, red, false);
    float m = s * (1.f/768.f);
    float d0 = v0-m, d1 = v1-m, d2 = v2-m;
    float q = blockReduce(d0*d0+d1*d1+d2*d2, red, false);
    float rstd = rsqrtf(q * (1.f/768.f) + 1e-5f);
    long long o = (long long)r * 768;
    xo[o+t]     = sig[o+t]     * (d0*rstd) + add[o+t];
    xo[o+t+256] = sig[o+t+256] * (d1*rstd) + add[o+t+256];
    xo[o+t+512] = sig[o+t+512] * (d2*rstd) + add[o+t+512];
}

__global__ void softmax_k(){
    long long r = blockIdx.x;
    float* p = g_lg + r * NN_;
    int t = threadIdx.x;
    __shared__ float red[32];
    float v0 = p[t], v1 = p[t+256], v2 = p[t+512];
    float mx = blockReduce(fmaxf(v0, fmaxf(v1, v2)), red, true);
    float e0 = expf(v0-mx), e1 = expf(v1-mx), e2 = expf(v2-mx);
    float s = blockReduce(e0+e1+e2, red, false);
    float inv = 1.f / s;
    p[t] = e0*inv; p[t+256] = e1*inv; p[t+512] = e2*inv;
}

__global__ void gatemul_k(){
    int i = blockIdx.x * 256 + threadIdx.x;
    if (i < NC_) g_wa[i] *= g_gate[i];
}

__global__ void glu_k(){
    int i = blockIdx.x * 256 + threadIdx.x;
    if (i >= NN_*FF_) return;
    int n = i / FF_, f = i % FF_;
    float u1 = g_u[(long long)n*2*FF_ + f];
    float u2 = g_u[(long long)n*2*FF_ + FF_ + f];
    g_c[i] = (u1 / (1.f + expf(-u1))) * u2;
}

// ---------------- host ----------------
static inline void gemm(int M, int N, int K,
    const float* A, int lda, long long sA,
    const float* B, int ldb, long long sB, int tB,
    float* C, int ldc, long long sC,
    int mode, const float* P1, long long sP1,
    const float* P2, long long sP2, float alpha, int batch)
{
    dim3 gr((N + 63) / 64, M / 64, batch);
    gemm_tc<<<gr, 256>>>(M, N, K, A, lda, sA, B, ldb, sB, tB, C, ldc, sC,
                         mode, P1, sP1, P2, sP2, alpha);
}

extern "C" void kernel_launch(void* const* d_in, const int* in_sizes, int n_in,
                              void* d_out, int out_size)
{
    const float* act         = (const float*)d_in[0];
    const float* mask        = (const float*)d_in[1];
    const float* single_cond = (const float*)d_in[2];
    const float* pair_cond   = (const float*)d_in[3];
    const float* attn_cln    = (const float*)d_in[4];
    const float* attn_cs_w   = (const float*)d_in[5];
    const float* attn_cs_b   = (const float*)d_in[6];
    const float* attn_cb_w   = (const float*)d_in[7];
    const float* q_w         = (const float*)d_in[8];
    const float* q_b         = (const float*)d_in[9];
    const float* k_w         = (const float*)d_in[10];
    const float* v_w         = (const float*)d_in[11];
    const float* gate_w      = (const float*)d_in[12];
    const float* gate_b      = (const float*)d_in[13];
    const float* out_w       = (const float*)d_in[14];
    const float* attn_azc_w  = (const float*)d_in[15];
    const float* attn_azc_b  = (const float*)d_in[16];
    const float* ffw_cln     = (const float*)d_in[17];
    const float* ffw_cs_w    = (const float*)d_in[18];
    const float* ffw_cs_b    = (const float*)d_in[19];
    const float* ffw_cb_w    = (const float*)d_in[20];
    const float* t1_w        = (const float*)d_in[21];
    const float* t2_w        = (const float*)d_in[22];
    const float* ffw_azc_w   = (const float*)d_in[23];
    const float* ffw_azc_b   = (const float*)d_in[24];
    const float* pair_lns    = (const float*)d_in[25];
    const float* pair_w      = (const float*)d_in[26];
    float* a = (float*)d_out;

    float *pl, *lg, *x, *qb, *kb, *vb, *gb, *wab, *ub, *cbb;
    float *cnA, *cnF, *sigA, *addA, *azcA, *sigF, *addF, *azcF, *bv;
    cudaGetSymbolAddress((void**)&pl,   g_pl);
    cudaGetSymbolAddress((void**)&lg,   g_lg);
    cudaGetSymbolAddress((void**)&x,    g_x);
    cudaGetSymbolAddress((void**)&qb,   g_q);
    cudaGetSymbolAddress((void**)&kb,   g_k);
    cudaGetSymbolAddress((void**)&vb,   g_v);
    cudaGetSymbolAddress((void**)&gb,   g_gate);
    cudaGetSymbolAddress((void**)&wab,  g_wa);
    cudaGetSymbolAddress((void**)&ub,   g_u);
    cudaGetSymbolAddress((void**)&cbb,  g_c);
    cudaGetSymbolAddress((void**)&cnA,  g_cnA);
    cudaGetSymbolAddress((void**)&cnF,  g_cnF);
    cudaGetSymbolAddress((void**)&sigA, g_sigA);
    cudaGetSymbolAddress((void**)&addA, g_addA);
    cudaGetSymbolAddress((void**)&azcA, g_azcA);
    cudaGetSymbolAddress((void**)&sigF, g_sigF);
    cudaGetSymbolAddress((void**)&addF, g_addF);
    cudaGetSymbolAddress((void**)&azcF, g_azcF);
    cudaGetSymbolAddress((void**)&bv,   g_bias);

    cudaMemcpyAsync(a, act, (size_t)NC_ * sizeof(float), cudaMemcpyDeviceToDevice);

    bias_k<<<3, 256>>>(mask);
    ln384_k<<<NN_, 128>>>(single_cond);
    cn_k<<<(LL_*NN_*CS_ + 255)/256, 256>>>(attn_cln, ffw_cln);

    cudaFuncSetAttribute(pair_k, cudaFuncAttributeMaxDynamicSharedMemorySize, 71168);
    pair_k<<<dim3(9216, 1, 2), 256, 71168>>>(pair_cond, pair_lns, pair_w);

    long long sNCS = (long long)NN_ * CS_;
    long long sWc  = (long long)CS_ * CC_;
    long long sNC  = (long long)NC_;
    gemm(768, 768, 384, cnA, 384, sNCS, attn_cs_w, 768, sWc, 0, sigA, 768, sNC, 2, attn_cs_b, 768, 0, 0, 0.f, 8);
    gemm(768, 768, 384, cnA, 384, sNCS, attn_cb_w, 768, sWc, 0, addA, 768, sNC, 0, 0, 0, 0, 0, 0.f, 8);
    gemm(768, 768, 384, single_cond, 384, 0, attn_azc_w, 768, sWc, 0, azcA, 768, sNC, 2, attn_azc_b, 768, 0, 0, 0.f, 8);
    gemm(768, 768, 384, cnF, 384, sNCS, ffw_cs_w, 768, sWc, 0, sigF, 768, sNC, 2, ffw_cs_b, 768, 0, 0, 0.f, 8);
    gemm(768, 768, 384, cnF, 384, sNCS, ffw_cb_w, 768, sWc, 0, addF, 768, sNC, 0, 0, 0, 0, 0, 0.f, 8);
    gemm(768, 768, 384, single_cond, 384, 0, ffw_azc_w, 768, sWc, 0, azcF, 768, sNC, 2, ffw_azc_b, 768, 0, 0, 0.f, 8);

    float al = 1.f / sqrtf(48.f);
    for (int l = 0; l < 8; l++){
        long long oNC = (long long)l * NC_;
        modulate_k<<<768, 256>>>(a, sigA + oNC, addA + oNC, x);
        gemm(768, 768, 768, x, 768, 0, q_w + oNC, 768, 0, 0, qb, 768, 0, 1, q_b + l*768, 0, 0, 0, 0.f, 1);
        gemm(768, 768, 768, x, 768, 0, k_w + oNC, 768, 0, 0, kb, 768, 0, 0, 0, 0, 0, 0, 0.f, 1);
        gemm(768, 768, 768, x, 768, 0, v_w + oNC, 768, 0, 0, vb, 768, 0, 0, 0, 0, 0, 0, 0.f, 1);
        gemm(768, 768, 768, x, 768, 0, gate_w + oNC, 768, 0, 0, gb, 768, 0, 2, gate_b + l*768, 0, 0, 0, 0.f, 1);
        gemm(768, 768, 48, qb, 768, 48, kb, 768, 48, 1, lg, 768, NNSQ_, 3,
             bv, 0, pl + (long long)l*HH_*NNSQ_, NNSQ_, al, 16);
        softmax_k<<<HH_*NN_, 256>>>();
        gemm(768, 48, 768, lg, 768, NNSQ_, vb, 768, 48, 0, wab, 768, 48, 0, 0, 0, 0, 0, 0.f, 16);
        gatemul_k<<<(NC_ + 255)/256, 256>>>();
        gemm(768, 768, 768, wab, 768, 0, out_w + oNC, 768, 0, 0, a, 768, 0, 4, azcA + oNC, 0, 0, 0, 0.f, 1);
        modulate_k<<<768, 256>>>(a, sigF + oNC, addF + oNC, x);
        gemm(768, 3072, 768, x, 768, 0, t1_w + (long long)l*768*3072, 3072, 0, 0, ub, 3072, 0, 0, 0, 0, 0, 0, 0.f, 1);
        glu_k<<<(NN_*FF_ + 255)/256, 256>>>();
        gemm(768, 768, 1536, cbb, 1536, 0, t2_w + (long long)l*1536*768, 768, 0, 0, a, 768, 0, 4, azcF + oNC, 0, 0, 0, 0.f, 1);
    }
    (void)in_sizes; (void)n_in; (void)out_size;
}

// round 3
// speedup vs baseline: 2.1260x; 1.2884x over previous
#include <cuda_runtime.h>
#include <cuda_bf16.h>
#include <math.h>

#define NN_ 768
#define CC_ 768
#define CS_ 384
#define CP_ 128
#define HH_ 16
#define KD_ 48
#define FF_ 1536
#define LL_ 8
#define NC_ (NN_*CC_)
#define NNSQ_ 589824LL

// ---------------- scratch ----------------
__device__ static __nv_bfloat16 g_pl[LL_*HH_*NN_*NN_];   // 151 MB pair logits bf16
__device__ static float g_x[NC_];
__device__ static float g_q[NC_], g_k[NC_], g_v[NC_], g_gate[NC_], g_wa[NC_];
__device__ static float g_u[NN_*2*FF_], g_c[NN_*FF_];
__device__ static float g_lnsc[NN_*CS_];
__device__ static float g_cnA[LL_*NN_*CS_], g_cnF[LL_*NN_*CS_];
__device__ static float g_sigA[LL_*NC_], g_addA[LL_*NC_], g_azcA[LL_*NC_];
__device__ static float g_sigF[LL_*NC_], g_addF[LL_*NC_], g_azcF[LL_*NC_];
__device__ static float g_bias[NN_];

// ---------------- tf32 mma helpers ----------------
__device__ __forceinline__ unsigned f2tf(float x){
    unsigned r; asm("cvt.rna.tf32.f32 %0, %1;" : "=r"(r) : "f"(x)); return r;
}
__device__ __forceinline__ void mma_tf32(float* c, const unsigned* a, unsigned b0, unsigned b1){
    asm volatile("mma.sync.aligned.m16n8k8.row.col.f32.tf32.tf32.f32 "
        "{%0,%1,%2,%3}, {%4,%5,%6,%7}, {%8,%9}, {%0,%1,%2,%3};\n"
        : "+f"(c[0]),"+f"(c[1]),"+f"(c[2]),"+f"(c[3])
        : "r"(a[0]),"r"(a[1]),"r"(a[2]),"r"(a[3]),"r"(b0),"r"(b1));
}

// ---------------- reductions ----------------
__device__ __forceinline__ float blockReduce(float v, float* red, bool ismax){
    __syncthreads();
    int lane = threadIdx.x & 31, w = threadIdx.x >> 5, nw = blockDim.x >> 5;
    #pragma unroll
    for (int o = 16; o; o >>= 1){
        float u = __shfl_xor_sync(0xffffffffu, v, o);
        v = ismax ? fmaxf(v, u) : v + u;
    }
    if (lane == 0) red[w] = v;
    __syncthreads();
    if (w == 0){
        v = (lane < nw) ? red[lane] : (ismax ? -1e30f : 0.f);
        #pragma unroll
        for (int o = 16; o; o >>= 1){
            float u = __shfl_xor_sync(0xffffffffu, v, o);
            v = ismax ? fmaxf(v, u) : v + u;
        }
        if (lane == 0) red[0] = v;
    }
    __syncthreads();
    return red[0];
}

// ---------------- epilogue ----------------
__device__ __forceinline__ void epi(float* C, int ldc, int mode,
    const float* P1, const float* P2, float alpha, int m, int n, int N, float r)
{
    if (n >= N) return;
    long long ci = (long long)m * ldc + n;
    if (mode == 0)      C[ci] = r;
    else if (mode == 1) C[ci] = r + P1[n];
    else if (mode == 2) C[ci] = 1.f / (1.f + expf(-(r + P1[n])));
    else if (mode == 3) C[ci] = r * alpha + P1[n] + P2[ci];
    else                C[ci] = C[ci] + P1[ci] * r;
}

// ---------------- shared tf32 GEMM body: 64x64 tile, BK=32, 256 threads ----------------
__device__ __forceinline__ void gemm64_body(int M, int N, int K,
    const float* __restrict__ A, int lda,
    const float* __restrict__ B, int ldb, int transB,
    float* __restrict__ C, int ldc,
    int mode, const float* __restrict__ P1, const float* __restrict__ P2, float alpha,
    unsigned* As, unsigned* Bs)
{
    int bm = blockIdx.y << 6, bn = blockIdx.x << 6;
    int t = threadIdx.x, lane = t & 31, w = t >> 5;
    int wm = w & 1, wn = w >> 1;

    int a_c = (t & 7) << 2;
    int a_r = t >> 3;
    int b_c = (t & 15) << 2;
    int b_r = t >> 4;
    int bt_c = (t & 7) << 2;
    int bt_r = t >> 3;

    float4 ra[2], rb[2];
    float acc[2][2][4];
    #pragma unroll
    for (int i = 0; i < 2; i++)
        #pragma unroll
        for (int j = 0; j < 2; j++)
            #pragma unroll
            for (int q = 0; q < 4; q++) acc[i][j][q] = 0.f;

    const float4 z4 = make_float4(0.f,0.f,0.f,0.f);

    #pragma unroll
    for (int i = 0; i < 2; i++){
        int row = bm + a_r + 32*i;
        ra[i] = (a_c < K) ? *(const float4*)&A[(long long)row * lda + a_c] : z4;
    }
    if (!transB){
        #pragma unroll
        for (int i = 0; i < 2; i++){
            int kr = b_r + 16*i; int n = bn + b_c;
            rb[i] = (kr < K && n < N) ? *(const float4*)&B[(long long)kr * ldb + n] : z4;
        }
    } else {
        #pragma unroll
        for (int i = 0; i < 2; i++){
            int nr = bn + bt_r + 32*i;
            rb[i] = (bt_c < K && nr < N) ? *(const float4*)&B[(long long)nr * ldb + bt_c] : z4;
        }
    }

    for (int k0 = 0;;){
        #pragma unroll
        for (int i = 0; i < 2; i++){
            uint4 u; u.x=f2tf(ra[i].x); u.y=f2tf(ra[i].y); u.z=f2tf(ra[i].z); u.w=f2tf(ra[i].w);
            *(uint4*)&As[(a_r + 32*i)*36 + a_c] = u;
        }
        if (!transB){
            #pragma unroll
            for (int i = 0; i < 2; i++){
                uint4 u; u.x=f2tf(rb[i].x); u.y=f2tf(rb[i].y); u.z=f2tf(rb[i].z); u.w=f2tf(rb[i].w);
                *(uint4*)&Bs[(b_r + 16*i)*72 + b_c] = u;
            }
        } else {
            #pragma unroll
            for (int i = 0; i < 2; i++){
                int nr = bt_r + 32*i;
                Bs[(bt_c+0)*72 + nr] = f2tf(rb[i].x);
                Bs[(bt_c+1)*72 + nr] = f2tf(rb[i].y);
                Bs[(bt_c+2)*72 + nr] = f2tf(rb[i].z);
                Bs[(bt_c+3)*72 + nr] = f2tf(rb[i].w);
            }
        }
        __syncthreads();

        int k1 = k0 + 32;
        if (k1 < K){
            #pragma unroll
            for (int i = 0; i < 2; i++){
                int row = bm + a_r + 32*i;
                ra[i] = (k1 + a_c < K) ? *(const float4*)&A[(long long)row * lda + k1 + a_c] : z4;
            }
            if (!transB){
                #pragma unroll
                for (int i = 0; i < 2; i++){
                    int kr = k1 + b_r + 16*i; int n = bn + b_c;
                    rb[i] = (kr < K && n < N) ? *(const float4*)&B[(long long)kr * ldb + n] : z4;
                }
            } else {
                #pragma unroll
                for (int i = 0; i < 2; i++){
                    int nr = bn + bt_r + 32*i;
                    rb[i] = (k1 + bt_c < K && nr < N) ? *(const float4*)&B[(long long)nr * ldb + k1 + bt_c] : z4;
                }
            }
        }

        #pragma unroll
        for (int k8 = 0; k8 < 32; k8 += 8){
            unsigned af[2][4], bf[2][2];
            #pragma unroll
            for (int mt = 0; mt < 2; mt++){
                int base = (wm*32 + mt*16 + (lane>>2))*36 + k8 + (lane&3);
                af[mt][0] = As[base];
                af[mt][1] = As[base + 8*36];
                af[mt][2] = As[base + 4];
                af[mt][3] = As[base + 8*36 + 4];
            }
            #pragma unroll
            for (int nt = 0; nt < 2; nt++){
                int bi = (k8 + (lane&3))*72 + wn*16 + nt*8 + (lane>>2);
                bf[nt][0] = Bs[bi];
                bf[nt][1] = Bs[bi + 4*72];
            }
            #pragma unroll
            for (int mt = 0; mt < 2; mt++)
                #pragma unroll
                for (int nt = 0; nt < 2; nt++)
                    mma_tf32(acc[mt][nt], af[mt], bf[nt][0], bf[nt][1]);
        }
        k0 = k1;
        if (k0 >= K) break;
        __syncthreads();
    }

    #pragma unroll
    for (int mt = 0; mt < 2; mt++){
        int r0 = bm + wm*32 + mt*16 + (lane>>2);
        #pragma unroll
        for (int nt = 0; nt < 2; nt++){
            int c0 = bn + wn*16 + nt*8 + 2*(lane&3);
            epi(C, ldc, mode, P1, P2, alpha, r0,   c0,   N, acc[mt][nt][0]);
            epi(C, ldc, mode, P1, P2, alpha, r0,   c0+1, N, acc[mt][nt][1]);
            epi(C, ldc, mode, P1, P2, alpha, r0+8, c0,   N, acc[mt][nt][2]);
            epi(C, ldc, mode, P1, P2, alpha, r0+8, c0+1, N, acc[mt][nt][3]);
        }
    }
}

__global__ void gemm_tc(int M, int N, int K,
    const float* __restrict__ A, int lda, long long sA,
    const float* __restrict__ B, int ldb, long long sB, int transB,
    float* __restrict__ C, int ldc, long long sC,
    int mode, const float* __restrict__ P1, long long sP1,
    const float* __restrict__ P2, long long sP2, float alpha)
{
    __shared__ unsigned As[64*36];
    __shared__ unsigned Bs[32*72];
    int bz = blockIdx.z;
    A += (long long)bz * sA;
    B += (long long)bz * sB;
    C += (long long)bz * sC;
    const float* P1b = P1 ? P1 + (long long)bz * sP1 : P1;
    const float* P2b = P2 ? P2 + (long long)bz * sP2 : P2;
    gemm64_body(M, N, K, A, lda, B, ldb, transB, C, ldc, mode, P1b, P2b, alpha, As, Bs);
}

// fused QKV+gate GEMM: z selects output
__global__ void qkvg_tc(const float* __restrict__ A,
    const float* __restrict__ Bq, const float* __restrict__ Bk,
    const float* __restrict__ Bv, const float* __restrict__ Bg,
    float* __restrict__ Cq, float* __restrict__ Ck,
    float* __restrict__ Cv, float* __restrict__ Cg,
    const float* __restrict__ biasq, const float* __restrict__ biasg)
{
    __shared__ unsigned As[64*36];
    __shared__ unsigned Bs[32*72];
    int z = blockIdx.z;
    const float* B = (z==0) ? Bq : (z==1) ? Bk : (z==2) ? Bv : Bg;
    float* C       = (z==0) ? Cq : (z==1) ? Ck : (z==2) ? Cv : Cg;
    int mode       = (z==0) ? 1 : (z==3) ? 2 : 0;
    const float* P1= (z==0) ? biasq : (z==3) ? biasg : (const float*)0;
    gemm64_body(768, 768, 768, A, 768, B, 768, 0, C, 768, mode, P1, (const float*)0, 0.f, As, Bs);
}

// ---------------- fused flash attention (tf32 mma), per (head, 64-row q-tile) ----------------
// S = (Q*scale)K^T + pl(bf16) + bias; online softmax; O = P V; out = gate * O / l
__global__ void flash_k(const float* __restrict__ qg, const float* __restrict__ kg,
                        const float* __restrict__ vg, const float* __restrict__ gateg,
                        const __nv_bfloat16* __restrict__ plg, float* __restrict__ og)
{
    extern __shared__ float fs[];
    float* Qs  = fs;                 // 64 x 52
    float* Ks  = Qs + 64*52;         // 64 x 60
    float* Vs  = Ks + 64*60;         // 64 x 56
    float* Ps  = Vs + 64*56;         // 64 x 68
    float* pls = Ps + 64*68;         // 64 x 68
    float* redm = pls + 64*68;       // 2 x 64
    float* reds = redm + 128;        // 2 x 64
    unsigned* Qsu = (unsigned*)Qs;
    unsigned* Ksu = (unsigned*)Ks;
    unsigned* Vsu = (unsigned*)Vs;
    unsigned* Psu = (unsigned*)Ps;

    const float scale = 0.14433756729740643f;  // 48^-0.5
    int h = blockIdx.x, qt = blockIdx.y;
    int q0 = qt * 64;
    int t = threadIdx.x, lane = t & 31, w = t >> 5;
    int wm = w & 3, wn = w >> 2;
    int r0l = wm*16 + (lane >> 2);
    int r1l = r0l + 8;

    // stage Q (scaled, tf32)
    for (int i = t; i < 768; i += 256){
        int r = i / 12, c4 = (i % 12) * 4;
        float4 v = *(const float4*)&qg[(long long)(q0 + r)*768 + h*48 + c4];
        Qsu[r*52 + c4+0] = f2tf(v.x * scale);
        Qsu[r*52 + c4+1] = f2tf(v.y * scale);
        Qsu[r*52 + c4+2] = f2tf(v.z * scale);
        Qsu[r*52 + c4+3] = f2tf(v.w * scale);
    }

    float m0o = -1e30f, m1o = -1e30f, l0 = 0.f, l1 = 0.f;
    float acc[6][4];
    #pragma unroll
    for (int i = 0; i < 6; i++)
        #pragma unroll
        for (int q = 0; q < 4; q++) acc[i][q] = 0.f;

    for (int kt = 0; kt < 12; kt++){
        int k0 = kt * 64;
        // stage K, V
        for (int i = t; i < 768; i += 256){
            int r = i / 12, c4 = (i % 12) * 4;
            float4 kv = *(const float4*)&kg[(long long)(k0 + r)*768 + h*48 + c4];
            Ksu[r*60 + c4+0] = f2tf(kv.x);
            Ksu[r*60 + c4+1] = f2tf(kv.y);
            Ksu[r*60 + c4+2] = f2tf(kv.z);
            Ksu[r*60 + c4+3] = f2tf(kv.w);
            float4 vv = *(const float4*)&vg[(long long)(k0 + r)*768 + h*48 + c4];
            Vsu[r*56 + c4+0] = f2tf(vv.x);
            Vsu[r*56 + c4+1] = f2tf(vv.y);
            Vsu[r*56 + c4+2] = f2tf(vv.z);
            Vsu[r*56 + c4+3] = f2tf(vv.w);
        }
        // stage pl (bf16) + bias
        for (int i = t; i < 512; i += 256){
            int e = i * 8;
            int r = e >> 6, c = e & 63;
            uint4 raw = *(const uint4*)&plg[((long long)h*768 + q0 + r)*768 + k0 + c];
            const unsigned* pu = &raw.x;
            #pragma unroll
            for (int j = 0; j < 4; j++){
                float2 f = __bfloat1622float2(*(const __nv_bfloat162*)&pu[j]);
                pls[r*68 + c + 2*j]     = f.x + g_bias[k0 + c + 2*j];
                pls[r*68 + c + 2*j + 1] = f.y + g_bias[k0 + c + 2*j + 1];
            }
        }
        __syncthreads();

        // S = Q K^T
        float s[4][4];
        #pragma unroll
        for (int i = 0; i < 4; i++)
            #pragma unroll
            for (int q = 0; q < 4; q++) s[i][q] = 0.f;
        #pragma unroll
        for (int kk = 0; kk < 48; kk += 8){
            unsigned a_[4];
            int ab = r0l*52 + kk + (lane & 3);
            a_[0] = Qsu[ab];
            a_[1] = Qsu[ab + 8*52];
            a_[2] = Qsu[ab + 4];
            a_[3] = Qsu[ab + 8*52 + 4];
            #pragma unroll
            for (int nt = 0; nt < 4; nt++){
                int bb = (wn*32 + nt*8 + (lane >> 2))*60 + kk + (lane & 3);
                mma_tf32(s[nt], a_, Ksu[bb], Ksu[bb + 4]);
            }
        }
        // add pl+bias, row max
        float rm0 = -1e30f, rm1 = -1e30f;
        #pragma unroll
        for (int nt = 0; nt < 4; nt++){
            int c = wn*32 + nt*8 + 2*(lane & 3);
            float2 p0 = *(float2*)&pls[r0l*68 + c];
            float2 p1 = *(float2*)&pls[r1l*68 + c];
            s[nt][0] += p0.x; s[nt][1] += p0.y;
            s[nt][2] += p1.x; s[nt][3] += p1.y;
            rm0 = fmaxf(rm0, fmaxf(s[nt][0], s[nt][1]));
            rm1 = fmaxf(rm1, fmaxf(s[nt][2], s[nt][3]));
        }
        rm0 = fmaxf(rm0, __shfl_xor_sync(0xffffffffu, rm0, 1));
        rm0 = fmaxf(rm0, __shfl_xor_sync(0xffffffffu, rm0, 2));
        rm1 = fmaxf(rm1, __shfl_xor_sync(0xffffffffu, rm1, 1));
        rm1 = fmaxf(rm1, __shfl_xor_sync(0xffffffffu, rm1, 2));
        if ((lane & 3) == 0){ redm[wn*64 + r0l] = rm0; redm[wn*64 + r1l] = rm1; }
        __syncthreads();
        float m0 = fmaxf(m0o, fmaxf(redm[r0l], redm[64 + r0l]));
        float m1 = fmaxf(m1o, fmaxf(redm[r1l], redm[64 + r1l]));
        float sc0 = __expf(m0o - m0), sc1 = __expf(m1o - m1);
        m0o = m0; m1o = m1;
        float rs0 = 0.f, rs1 = 0.f;
        #pragma unroll
        for (int nt = 0; nt < 4; nt++){
            int c = wn*32 + nt*8 + 2*(lane & 3);
            float p00 = __expf(s[nt][0] - m0), p01 = __expf(s[nt][1] - m0);
            float p10 = __expf(s[nt][2] - m1), p11 = __expf(s[nt][3] - m1);
            rs0 += p00 + p01; rs1 += p10 + p11;
            uint2 u0; u0.x = f2tf(p00); u0.y = f2tf(p01);
            *(uint2*)&Psu[r0l*68 + c] = u0;
            uint2 u1; u1.x = f2tf(p10); u1.y = f2tf(p11);
            *(uint2*)&Psu[r1l*68 + c] = u1;
        }
        rs0 += __shfl_xor_sync(0xffffffffu, rs0, 1);
        rs0 += __shfl_xor_sync(0xffffffffu, rs0, 2);
        rs1 += __shfl_xor_sync(0xffffffffu, rs1, 1);
        rs1 += __shfl_xor_sync(0xffffffffu, rs1, 2);
        if ((lane & 3) == 0){ reds[wn*64 + r0l] = rs0; reds[wn*64 + r1l] = rs1; }
        #pragma unroll
        for (int nt = 0; nt < 6; nt++){
            acc[nt][0] *= sc0; acc[nt][1] *= sc0;
            acc[nt][2] *= sc1; acc[nt][3] *= sc1;
        }
        __syncthreads();
        l0 = l0 * sc0 + reds[r0l] + reds[64 + r0l];
        l1 = l1 * sc1 + reds[r1l] + reds[64 + r1l];
        // O += P V  (this warp covers kv range wn*32..wn*32+32)
        #pragma unroll
        for (int kk = 0; kk < 32; kk += 8){
            unsigned a_[4];
            int ab = r0l*68 + wn*32 + kk + (lane & 3);
            a_[0] = Psu[ab];
            a_[1] = Psu[ab + 8*68];
            a_[2] = Psu[ab + 4];
            a_[3] = Psu[ab + 8*68 + 4];
            #pragma unroll
            for (int nt = 0; nt < 6; nt++){
                int bb = (wn*32 + kk + (lane & 3))*56 + nt*8 + (lane >> 2);
                mma_tf32(acc[nt], a_, Vsu[bb], Vsu[bb + 4*56]);
            }
        }
        __syncthreads();
    }

    // combine the two kv-half partial O's (reuse Ps region)
    if (wn == 1){
        #pragma unroll
        for (int nt = 0; nt < 6; nt++){
            int c = nt*8 + 2*(lane & 3);
            *(float2*)&Ps[r0l*52 + c] = make_float2(acc[nt][0], acc[nt][1]);
            *(float2*)&Ps[r1l*52 + c] = make_float2(acc[nt][2], acc[nt][3]);
        }
    }
    __syncthreads();
    if (wn == 0){
        float inv0 = 1.f / l0, inv1 = 1.f / l1;
        #pragma unroll
        for (int nt = 0; nt < 6; nt++){
            int c = nt*8 + 2*(lane & 3);
            float2 o0 = *(float2*)&Ps[r0l*52 + c];
            float2 o1 = *(float2*)&Ps[r1l*52 + c];
            long long gidx0 = (long long)(q0 + r0l)*768 + h*48 + c;
            long long gidx1 = (long long)(q0 + r1l)*768 + h*48 + c;
            float2 gt0 = *(const float2*)&gateg[gidx0];
            float2 gt1 = *(const float2*)&gateg[gidx1];
            float2 out0; out0.x = (acc[nt][0] + o0.x) * inv0 * gt0.x;
                         out0.y = (acc[nt][1] + o0.y) * inv0 * gt0.y;
            float2 out1; out1.x = (acc[nt][2] + o1.x) * inv1 * gt1.x;
                         out1.y = (acc[nt][3] + o1.y) * inv1 * gt1.y;
            *(float2*)&og[gidx0] = out0;
            *(float2*)&og[gidx1] = out1;
        }
    }
}

// ---------------- fused pair LN + pl GEMM (tf32 mma, bf16 out) ----------------
__global__ void pair_k(const float* __restrict__ pc, const float* __restrict__ scale,
                       const float* __restrict__ pw)
{
    extern __shared__ unsigned sm[];
    unsigned* spc = sm;                    // 64 x 132
    unsigned* spw = sm + 64*132;           // 128 x 72
    float*    ssc = (float*)(sm + 64*132 + 128*72);
    int nsb = blockIdx.z;
    int t = threadIdx.x, lane = t & 31, w = t >> 5;
    long long row0 = (long long)blockIdx.x * 64;

    for (int i = t; i < 128*64; i += 256){
        int c = i >> 6, n = i & 63;
        spw[c*72 + n] = f2tf(pw[nsb*8192 + i]);
    }
    if (t < 128) ssc[t] = scale[t];
    for (int i = t; i < 64*128; i += 256){
        int r = i >> 7, c = i & 127;
        spc[r*132 + c] = __float_as_uint(pc[(row0 + r)*128 + c]);
    }
    __syncthreads();

    for (int rr = 0; rr < 8; rr++){
        int r = w*8 + rr;
        unsigned* pr = spc + r*132;
        float x0 = __uint_as_float(pr[lane]);
        float x1 = __uint_as_float(pr[lane+32]);
        float x2 = __uint_as_float(pr[lane+64]);
        float x3 = __uint_as_float(pr[lane+96]);
        float s = x0+x1+x2+x3;
        #pragma unroll
        for (int o = 16; o; o >>= 1) s += __shfl_xor_sync(0xffffffffu, s, o);
        float m = s * (1.f/128.f);
        x0 -= m; x1 -= m; x2 -= m; x3 -= m;
        float vq = x0*x0+x1*x1+x2*x2+x3*x3;
        #pragma unroll
        for (int o = 16; o; o >>= 1) vq += __shfl_xor_sync(0xffffffffu, vq, o);
        float rstd = rsqrtf(vq * (1.f/128.f) + 1e-5f);
        pr[lane]    = f2tf(x0*rstd*ssc[lane]);
        pr[lane+32] = f2tf(x1*rstd*ssc[lane+32]);
        pr[lane+64] = f2tf(x2*rstd*ssc[lane+64]);
        pr[lane+96] = f2tf(x3*rstd*ssc[lane+96]);
    }
    __syncthreads();

    int wm = w & 3, wn = w >> 2;
    float acc[4][4];
    #pragma unroll
    for (int i = 0; i < 4; i++)
        #pragma unroll
        for (int q = 0; q < 4; q++) acc[i][q] = 0.f;

    #pragma unroll 4
    for (int k8 = 0; k8 < 128; k8 += 8){
        unsigned af[4];
        int base = (wm*16 + (lane>>2))*132 + k8 + (lane&3);
        af[0] = spc[base];
        af[1] = spc[base + 8*132];
        af[2] = spc[base + 4];
        af[3] = spc[base + 8*132 + 4];
        #pragma unroll
        for (int nt = 0; nt < 4; nt++){
            int bi = (k8 + (lane&3))*72 + wn*32 + nt*8 + (lane>>2);
            mma_tf32(acc[nt], af, spw[bi], spw[bi + 4*72]);
        }
    }
    __syncthreads();

    float* sout = (float*)spw;  // 64 x 68
    int r = wm*16 + (lane>>2);
    #pragma unroll
    for (int nt = 0; nt < 4; nt++){
        int c = wn*32 + nt*8 + 2*(lane&3);
        sout[(c  )*68 + r    ] = acc[nt][0];
        sout[(c+1)*68 + r    ] = acc[nt][1];
        sout[(c  )*68 + r + 8] = acc[nt][2];
        sout[(c+1)*68 + r + 8] = acc[nt][3];
    }
    __syncthreads();
    for (int i = t; i < 4096; i += 256){
        int col = i >> 6, m = i & 63;
        g_pl[((long long)(nsb*64 + col))*NNSQ_ + row0 + m] = __float2bfloat16(sout[col*68 + m]);
    }
}

// ---------------- small kernels ----------------
__global__ void bias_k(const float* __restrict__ mask){
    int i = blockIdx.x * 256 + threadIdx.x;
    if (i < NN_) g_bias[i] = 1e9f * (mask[i] - 1.f);
}

__global__ void ln384_k(const float* __restrict__ in){
    int r = blockIdx.x, t = threadIdx.x;
    __shared__ float red[32];
    const float* p = in + (long long)r * CS_;
    float v0 = p[t], v1 = p[t+128], v2 = p[t+256];
    float s = blockReduce(v0+v1+v2, red, false);
    float m = s * (1.f/384.f);
    float d0 = v0-m, d1 = v1-m, d2 = v2-m;
    float q = blockReduce(d0*d0+d1*d1+d2*d2, red, false);
    float rstd = rsqrtf(q * (1.f/384.f) + 1e-5f);
    float* o = g_lnsc + (long long)r * CS_;
    o[t] = d0*rstd; o[t+128] = d1*rstd; o[t+256] = d2*rstd;
}

__global__ void cn_k(const float* __restrict__ aln, const float* __restrict__ fln){
    int i = blockIdx.x * 256 + threadIdx.x;
    if (i >= LL_*NN_*CS_) return;
    int l = i / (NN_*CS_);
    int rem = i % (NN_*CS_);
    int c = rem % CS_;
    float b = g_lnsc[rem];
    g_cnA[i] = b * aln[l*CS_ + c];
    g_cnF[i] = b * fln[l*CS_ + c];
}

__global__ void modulate_k(const float* __restrict__ a, const float* __restrict__ sig,
                           const float* __restrict__ add, float* __restrict__ xo){
    int r = blockIdx.x, t = threadIdx.x;
    __shared__ float red[32];
    const float* ar = a + (long long)r * 768;
    float v0 = ar[t], v1 = ar[t+256], v2 = ar[t+512];
    float s = blockReduce(v0+v1+v2, red, false);
    float m = s * (1.f/768.f);
    float d0 = v0-m, d1 = v1-m, d2 = v2-m;
    float q = blockReduce(d0*d0+d1*d1+d2*d2, red, false);
    float rstd = rsqrtf(q * (1.f/768.f) + 1e-5f);
    long long o = (long long)r * 768;
    xo[o+t]     = sig[o+t]     * (d0*rstd) + add[o+t];
    xo[o+t+256] = sig[o+t+256] * (d1*rstd) + add[o+t+256];
    xo[o+t+512] = sig[o+t+512] * (d2*rstd) + add[o+t+512];
}

__global__ void glu_k(){
    int i = blockIdx.x * 256 + threadIdx.x;
    if (i >= NN_*FF_) return;
    int n = i / FF_, f = i % FF_;
    float u1 = g_u[(long long)n*2*FF_ + f];
    float u2 = g_u[(long long)n*2*FF_ + FF_ + f];
    g_c[i] = (u1 / (1.f + expf(-u1))) * u2;
}

// ---------------- host ----------------
static inline void gemm(int M, int N, int K,
    const float* A, int lda, long long sA,
    const float* B, int ldb, long long sB, int tB,
    float* C, int ldc, long long sC,
    int mode, const float* P1, long long sP1,
    const float* P2, long long sP2, float alpha, int batch)
{
    dim3 gr((N + 63) / 64, M / 64, batch);
    gemm_tc<<<gr, 256>>>(M, N, K, A, lda, sA, B, ldb, sB, tB, C, ldc, sC,
                         mode, P1, sP1, P2, sP2, alpha);
}

extern "C" void kernel_launch(void* const* d_in, const int* in_sizes, int n_in,
                              void* d_out, int out_size)
{
    const float* act         = (const float*)d_in[0];
    const float* mask        = (const float*)d_in[1];
    const float* single_cond = (const float*)d_in[2];
    const float* pair_cond   = (const float*)d_in[3];
    const float* attn_cln    = (const float*)d_in[4];
    const float* attn_cs_w   = (const float*)d_in[5];
    const float* attn_cs_b   = (const float*)d_in[6];
    const float* attn_cb_w   = (const float*)d_in[7];
    const float* q_w         = (const float*)d_in[8];
    const float* q_b         = (const float*)d_in[9];
    const float* k_w         = (const float*)d_in[10];
    const float* v_w         = (const float*)d_in[11];
    const float* gate_w      = (const float*)d_in[12];
    const float* gate_b      = (const float*)d_in[13];
    const float* out_w       = (const float*)d_in[14];
    const float* attn_azc_w  = (const float*)d_in[15];
    const float* attn_azc_b  = (const float*)d_in[16];
    const float* ffw_cln     = (const float*)d_in[17];
    const float* ffw_cs_w    = (const float*)d_in[18];
    const float* ffw_cs_b    = (const float*)d_in[19];
    const float* ffw_cb_w    = (const float*)d_in[20];
    const float* t1_w        = (const float*)d_in[21];
    const float* t2_w        = (const float*)d_in[22];
    const float* ffw_azc_w   = (const float*)d_in[23];
    const float* ffw_azc_b   = (const float*)d_in[24];
    const float* pair_lns    = (const float*)d_in[25];
    const float* pair_w      = (const float*)d_in[26];
    float* a = (float*)d_out;

    __nv_bfloat16* pl;
    float *x, *qb, *kb, *vb, *gb, *wab, *ub, *cbb;
    float *cnA, *cnF, *sigA, *addA, *azcA, *sigF, *addF, *azcF;
    cudaGetSymbolAddress((void**)&pl,   g_pl);
    cudaGetSymbolAddress((void**)&x,    g_x);
    cudaGetSymbolAddress((void**)&qb,   g_q);
    cudaGetSymbolAddress((void**)&kb,   g_k);
    cudaGetSymbolAddress((void**)&vb,   g_v);
    cudaGetSymbolAddress((void**)&gb,   g_gate);
    cudaGetSymbolAddress((void**)&wab,  g_wa);
    cudaGetSymbolAddress((void**)&ub,   g_u);
    cudaGetSymbolAddress((void**)&cbb,  g_c);
    cudaGetSymbolAddress((void**)&cnA,  g_cnA);
    cudaGetSymbolAddress((void**)&cnF,  g_cnF);
    cudaGetSymbolAddress((void**)&sigA, g_sigA);
    cudaGetSymbolAddress((void**)&addA, g_addA);
    cudaGetSymbolAddress((void**)&azcA, g_azcA);
    cudaGetSymbolAddress((void**)&sigF, g_sigF);
    cudaGetSymbolAddress((void**)&addF, g_addF);
    cudaGetSymbolAddress((void**)&azcF, g_azcF);

    cudaMemcpyAsync(a, act, (size_t)NC_ * sizeof(float), cudaMemcpyDeviceToDevice);

    bias_k<<<3, 256>>>(mask);
    ln384_k<<<NN_, 128>>>(single_cond);
    cn_k<<<(LL_*NN_*CS_ + 255)/256, 256>>>(attn_cln, ffw_cln);

    cudaFuncSetAttribute(pair_k, cudaFuncAttributeMaxDynamicSharedMemorySize, 71168);
    pair_k<<<dim3(9216, 1, 2), 256, 71168>>>(pair_cond, pair_lns, pair_w);

    long long sNCS = (long long)NN_ * CS_;
    long long sWc  = (long long)CS_ * CC_;
    long long sNC  = (long long)NC_;
    gemm(768, 768, 384, cnA, 384, sNCS, attn_cs_w, 768, sWc, 0, sigA, 768, sNC, 2, attn_cs_b, 768, 0, 0, 0.f, 8);
    gemm(768, 768, 384, cnA, 384, sNCS, attn_cb_w, 768, sWc, 0, addA, 768, sNC, 0, 0, 0, 0, 0, 0.f, 8);
    gemm(768, 768, 384, single_cond, 384, 0, attn_azc_w, 768, sWc, 0, azcA, 768, sNC, 2, attn_azc_b, 768, 0, 0, 0.f, 8);
    gemm(768, 768, 384, cnF, 384, sNCS, ffw_cs_w, 768, sWc, 0, sigF, 768, sNC, 2, ffw_cs_b, 768, 0, 0, 0.f, 8);
    gemm(768, 768, 384, cnF, 384, sNCS, ffw_cb_w, 768, sWc, 0, addF, 768, sNC, 0, 0, 0, 0, 0, 0.f, 8);
    gemm(768, 768, 384, single_cond, 384, 0, ffw_azc_w, 768, sWc, 0, azcF, 768, sNC, 2, ffw_azc_b, 768, 0, 0, 0.f, 8);

    cudaFuncSetAttribute(flash_k, cudaFuncAttributeMaxDynamicSharedMemorySize, 78848);

    for (int l = 0; l < 8; l++){
        long long oNC = (long long)l * NC_;
        modulate_k<<<768, 256>>>(a, sigA + oNC, addA + oNC, x);
        qkvg_tc<<<dim3(12, 12, 4), 256>>>(x,
            q_w + oNC, k_w + oNC, v_w + oNC, gate_w + oNC,
            qb, kb, vb, gb, q_b + l*768, gate_b + l*768);
        flash_k<<<dim3(16, 12), 256, 78848>>>(qb, kb, vb, gb,
            pl + (long long)l * HH_ * NNSQ_, wab);
        gemm(768, 768, 768, wab, 768, 0, out_w + oNC, 768, 0, 0, a, 768, 0, 4, azcA + oNC, 0, 0, 0, 0.f, 1);
        modulate_k<<<768, 256>>>(a, sigF + oNC, addF + oNC, x);
        gemm(768, 3072, 768, x, 768, 0, t1_w + (long long)l*768*3072, 3072, 0, 0, ub, 3072, 0, 0, 0, 0, 0, 0, 0.f, 1);
        glu_k<<<(NN_*FF_ + 255)/256, 256>>>();
        gemm(768, 768, 1536, cbb, 1536, 0, t2_w + (long long)l*1536*768, 768, 0, 0, a, 768, 0, 4, azcF + oNC, 0, 0, 0, 0.f, 1);
    }
    (void)in_sizes; (void)n_in; (void)out_size;
}

// round 4
// speedup vs baseline: 3.0764x; 1.4470x over previous
#include <cuda_runtime.h>
#include <cuda_bf16.h>
#include <math.h>

#define NN_ 768
#define CC_ 768
#define CS_ 384
#define HH_ 16
#define FF_ 1536
#define LL_ 8
#define NC_ (NN_*CC_)
#define NNSQ_ 589824LL

// ---------------- scratch ----------------
__device__ static __nv_bfloat16 g_pl[LL_*HH_*NN_*NN_];
__device__ static float g_x[NC_];
__device__ static float g_q[NC_], g_k[NC_], g_v[NC_], g_gate[NC_], g_wa[NC_];
__device__ static float g_u[NN_*2*FF_], g_c[NN_*FF_];
__device__ static float g_lnsc[NN_*CS_];
__device__ static float g_cnA[LL_*NN_*CS_], g_cnF[LL_*NN_*CS_];
__device__ static float g_sigA[LL_*NC_], g_addA[LL_*NC_], g_azcA[LL_*NC_];
__device__ static float g_sigF[LL_*NC_], g_addF[LL_*NC_], g_azcF[LL_*NC_];
__device__ static float g_bias[NN_];

// ---------------- bf16 mma helpers ----------------
__device__ __forceinline__ unsigned f2bf2(float lo, float hi){
    unsigned r; asm("cvt.rn.bf16x2.f32 %0, %1, %2;" : "=r"(r) : "f"(hi), "f"(lo)); return r;
}
__device__ __forceinline__ unsigned s2u(const void* p){
    return (unsigned)__cvta_generic_to_shared(p);
}
__device__ __forceinline__ void ldsm4(unsigned* r, unsigned a){
    asm volatile("ldmatrix.sync.aligned.m8n8.x4.shared.b16 {%0,%1,%2,%3}, [%4];"
        : "=r"(r[0]),"=r"(r[1]),"=r"(r[2]),"=r"(r[3]) : "r"(a));
}
__device__ __forceinline__ void ldsm2(unsigned* r, unsigned a){
    asm volatile("ldmatrix.sync.aligned.m8n8.x2.shared.b16 {%0,%1}, [%2];"
        : "=r"(r[0]),"=r"(r[1]) : "r"(a));
}
__device__ __forceinline__ void ldsm2t(unsigned* r, unsigned a){
    asm volatile("ldmatrix.sync.aligned.m8n8.x2.trans.shared.b16 {%0,%1}, [%2];"
        : "=r"(r[0]),"=r"(r[1]) : "r"(a));
}
__device__ __forceinline__ void mma_bf16(float* c, const unsigned* a, const unsigned* b){
    asm volatile("mma.sync.aligned.m16n8k16.row.col.f32.bf16.bf16.f32 "
        "{%0,%1,%2,%3}, {%4,%5,%6,%7}, {%8,%9}, {%0,%1,%2,%3};"
        : "+f"(c[0]),"+f"(c[1]),"+f"(c[2]),"+f"(c[3])
        : "r"(a[0]),"r"(a[1]),"r"(a[2]),"r"(a[3]),"r"(b[0]),"r"(b[1]));
}

// ---------------- reductions ----------------
__device__ __forceinline__ float blockReduce(float v, float* red, bool ismax){
    __syncthreads();
    int lane = threadIdx.x & 31, w = threadIdx.x >> 5, nw = blockDim.x >> 5;
    #pragma unroll
    for (int o = 16; o; o >>= 1){
        float u = __shfl_xor_sync(0xffffffffu, v, o);
        v = ismax ? fmaxf(v, u) : v + u;
    }
    if (lane == 0) red[w] = v;
    __syncthreads();
    if (w == 0){
        v = (lane < nw) ? red[lane] : (ismax ? -1e30f : 0.f);
        #pragma unroll
        for (int o = 16; o; o >>= 1){
            float u = __shfl_xor_sync(0xffffffffu, v, o);
            v = ismax ? fmaxf(v, u) : v + u;
        }
        if (lane == 0) red[0] = v;
    }
    __syncthreads();
    return red[0];
}

// ---------------- epilogue ----------------
__device__ __forceinline__ void epi(float* C, int ldc, int mode,
    const float* P1, int m, int n, float r)
{
    long long ci = (long long)m * ldc + n;
    if (mode == 0)      C[ci] = r;
    else if (mode == 1) C[ci] = r + P1[n];
    else if (mode == 2) C[ci] = 1.f / (1.f + expf(-(r + P1[n])));
    else                C[ci] = C[ci] + P1[ci] * r;
}

// ---------------- bf16 GEMM body: 64x64 tile, BK=32, 256 threads, double-buffered ----------------
// A row-major [M,K]; B row-major [K,N]. M,N mult of 64; K mult of 32.
__device__ __forceinline__ void gemm64_body(int K,
    const float* __restrict__ A, int lda,
    const float* __restrict__ B, int ldb,
    float* __restrict__ C, int ldc,
    int mode, const float* __restrict__ P1,
    __nv_bfloat16* Asb, __nv_bfloat16* Bsb)
{
    int bm = blockIdx.y << 6, bn = blockIdx.x << 6;
    int t = threadIdx.x, lane = t & 31, w = t >> 5;
    int wm = w & 1, wn = w >> 1;
    int a_r = t >> 3, a_c = (t & 7) << 2;
    int b_r = t >> 4, b_c = (t & 15) << 2;
    int arow = ((lane >> 3) & 1) * 8 + (lane & 7);
    int acol = (lane >> 4) << 3;

    float acc[2][2][4];
    #pragma unroll
    for (int i = 0; i < 2; i++)
        #pragma unroll
        for (int j = 0; j < 2; j++)
            #pragma unroll
            for (int q = 0; q < 4; q++) acc[i][j][q] = 0.f;

    float4 ra0 = *(const float4*)&A[(long long)(bm + a_r)*lda + a_c];
    float4 ra1 = *(const float4*)&A[(long long)(bm + a_r + 32)*lda + a_c];
    float4 rb0 = *(const float4*)&B[(long long)b_r*ldb + bn + b_c];
    float4 rb1 = *(const float4*)&B[(long long)(b_r + 16)*ldb + bn + b_c];

    int nk = K >> 5;
    for (int it = 0;;){
        __nv_bfloat16* As = Asb + (it & 1) * (64*40);
        __nv_bfloat16* Bs = Bsb + (it & 1) * (32*72);
        uint2 u;
        u.x = f2bf2(ra0.x, ra0.y); u.y = f2bf2(ra0.z, ra0.w);
        *(uint2*)&As[a_r*40 + a_c] = u;
        u.x = f2bf2(ra1.x, ra1.y); u.y = f2bf2(ra1.z, ra1.w);
        *(uint2*)&As[(a_r + 32)*40 + a_c] = u;
        u.x = f2bf2(rb0.x, rb0.y); u.y = f2bf2(rb0.z, rb0.w);
        *(uint2*)&Bs[b_r*72 + b_c] = u;
        u.x = f2bf2(rb1.x, rb1.y); u.y = f2bf2(rb1.z, rb1.w);
        *(uint2*)&Bs[(b_r + 16)*72 + b_c] = u;
        __syncthreads();

        int itn = it + 1;
        if (itn < nk){
            int k1 = itn << 5;
            ra0 = *(const float4*)&A[(long long)(bm + a_r)*lda + k1 + a_c];
            ra1 = *(const float4*)&A[(long long)(bm + a_r + 32)*lda + k1 + a_c];
            rb0 = *(const float4*)&B[(long long)(k1 + b_r)*ldb + bn + b_c];
            rb1 = *(const float4*)&B[(long long)(k1 + b_r + 16)*ldb + bn + b_c];
        }

        unsigned aB = s2u(As), bB = s2u(Bs);
        #pragma unroll
        for (int k16 = 0; k16 < 32; k16 += 16){
            unsigned af[2][4], bf[2][2];
            #pragma unroll
            for (int mt = 0; mt < 2; mt++)
                ldsm4(af[mt], aB + ((wm*32 + mt*16 + arow)*40 + k16 + acol)*2);
            #pragma unroll
            for (int nt = 0; nt < 2; nt++)
                ldsm2t(bf[nt], bB + ((k16 + (lane & 15))*72 + wn*16 + nt*8)*2);
            #pragma unroll
            for (int mt = 0; mt < 2; mt++)
                #pragma unroll
                for (int nt = 0; nt < 2; nt++)
                    mma_bf16(acc[mt][nt], af[mt], bf[nt]);
        }
        it = itn;
        if (it >= nk) break;
    }

    #pragma unroll
    for (int mt = 0; mt < 2; mt++){
        int r0 = bm + wm*32 + mt*16 + (lane >> 2);
        #pragma unroll
        for (int nt = 0; nt < 2; nt++){
            int c0 = bn + wn*16 + nt*8 + 2*(lane & 3);
            float* ac = acc[mt][nt];
            epi(C, ldc, mode, P1, r0,   c0,   ac[0]);
            epi(C, ldc, mode, P1, r0,   c0+1, ac[1]);
            epi(C, ldc, mode, P1, r0+8, c0,   ac[2]);
            epi(C, ldc, mode, P1, r0+8, c0+1, ac[3]);
        }
    }
}

__global__ void gemm_tc(int K,
    const float* __restrict__ A, int lda, long long sA,
    const float* __restrict__ B, int ldb, long long sB,
    float* __restrict__ C, int ldc, long long sC,
    int mode, const float* __restrict__ P1, long long sP1)
{
    __shared__ __align__(16) __nv_bfloat16 As[2*64*40];
    __shared__ __align__(16) __nv_bfloat16 Bs[2*32*72];
    int bz = blockIdx.z;
    gemm64_body(K, A + (long long)bz*sA, lda, B + (long long)bz*sB, ldb,
                C + (long long)bz*sC, ldc, mode,
                P1 ? P1 + (long long)bz*sP1 : P1, As, Bs);
}

__global__ void qkvg_tc(const float* __restrict__ A,
    const float* __restrict__ Bq, const float* __restrict__ Bk,
    const float* __restrict__ Bv, const float* __restrict__ Bg,
    float* __restrict__ Cq, float* __restrict__ Ck,
    float* __restrict__ Cv, float* __restrict__ Cg,
    const float* __restrict__ biasq, const float* __restrict__ biasg)
{
    __shared__ __align__(16) __nv_bfloat16 As[2*64*40];
    __shared__ __align__(16) __nv_bfloat16 Bs[2*32*72];
    int z = blockIdx.z;
    const float* B = (z==0) ? Bq : (z==1) ? Bk : (z==2) ? Bv : Bg;
    float* C       = (z==0) ? Cq : (z==1) ? Ck : (z==2) ? Cv : Cg;
    int mode       = (z==0) ? 1 : (z==3) ? 2 : 0;
    const float* P1= (z==0) ? biasq : (z==3) ? biasg : (const float*)0;
    gemm64_body(768, A, 768, B, 768, C, 768, mode, P1, As, Bs);
}

// ---------------- fused flash attention (bf16 mma) ----------------
__global__ void flash_k(const float* __restrict__ qg, const float* __restrict__ kg,
                        const float* __restrict__ vg, const float* __restrict__ gateg,
                        const __nv_bfloat16* __restrict__ plg, float* __restrict__ og)
{
    extern __shared__ __align__(16) char fsm[];
    __nv_bfloat16* Qs = (__nv_bfloat16*)fsm;           // 64x56
    __nv_bfloat16* Ks = Qs + 64*56;                    // 64x56
    __nv_bfloat16* Vs = Ks + 64*56;                    // 64x56
    __nv_bfloat16* Ps = Vs + 64*56;                    // 64x72
    float* pls  = (float*)(Ps + 64*72);                // 64x68 (reused as Of 64x52)
    float* redm = pls + 64*68;                         // 2x64
    float* reds = redm + 128;                          // 2x64

    const float scale = 0.14433756729740643f;
    int h = blockIdx.x, q0 = blockIdx.y * 64;
    int t = threadIdx.x, lane = t & 31, w = t >> 5;
    int wm = w & 3, wn = w >> 2;
    int r0l = wm*16 + (lane >> 2), r1l = r0l + 8;
    int arow = ((lane >> 3) & 1) * 8 + (lane & 7);
    int acol = (lane >> 4) << 3;

    // stage Q (scaled, bf16)
    for (int i = t; i < 768; i += 256){
        int r = i / 12, c4 = (i % 12) * 4;
        float4 v = *(const float4*)&qg[(long long)(q0 + r)*768 + h*48 + c4];
        uint2 u; u.x = f2bf2(v.x*scale, v.y*scale); u.y = f2bf2(v.z*scale, v.w*scale);
        *(uint2*)&Qs[r*56 + c4] = u;
    }
    __syncthreads();
    unsigned qB = s2u(Qs), kB = s2u(Ks), vB = s2u(Vs), pB = s2u(Ps);
    unsigned aq[3][4];
    #pragma unroll
    for (int kk = 0; kk < 3; kk++)
        ldsm4(aq[kk], qB + ((wm*16 + arow)*56 + kk*16 + acol)*2);

    float m0o = -1e30f, m1o = -1e30f, l0 = 0.f, l1 = 0.f;
    float acc[6][4];
    #pragma unroll
    for (int i = 0; i < 6; i++)
        #pragma unroll
        for (int q = 0; q < 4; q++) acc[i][q] = 0.f;

    for (int kt = 0; kt < 12; kt++){
        int k0 = kt * 64;
        for (int i = t; i < 768; i += 256){
            int r = i / 12, c4 = (i % 12) * 4;
            float4 kv = *(const float4*)&kg[(long long)(k0 + r)*768 + h*48 + c4];
            uint2 u; u.x = f2bf2(kv.x, kv.y); u.y = f2bf2(kv.z, kv.w);
            *(uint2*)&Ks[r*56 + c4] = u;
            float4 vv = *(const float4*)&vg[(long long)(k0 + r)*768 + h*48 + c4];
            u.x = f2bf2(vv.x, vv.y); u.y = f2bf2(vv.z, vv.w);
            *(uint2*)&Vs[r*56 + c4] = u;
        }
        for (int i = t; i < 512; i += 256){
            int e = i * 8;
            int r = e >> 6, c = e & 63;
            uint4 raw = *(const uint4*)&plg[((long long)h*768 + q0 + r)*768 + k0 + c];
            const unsigned* pu = &raw.x;
            #pragma unroll
            for (int j = 0; j < 4; j++){
                float2 f = __bfloat1622float2(*(const __nv_bfloat162*)&pu[j]);
                pls[r*68 + c + 2*j]     = f.x + g_bias[k0 + c + 2*j];
                pls[r*68 + c + 2*j + 1] = f.y + g_bias[k0 + c + 2*j + 1];
            }
        }
        __syncthreads();

        // S = Q K^T
        float s[4][4];
        #pragma unroll
        for (int i = 0; i < 4; i++)
            #pragma unroll
            for (int q = 0; q < 4; q++) s[i][q] = 0.f;
        #pragma unroll
        for (int kk = 0; kk < 3; kk++){
            #pragma unroll
            for (int nt = 0; nt < 4; nt++){
                unsigned bk[2];
                ldsm2(bk, kB + ((wn*32 + nt*8 + (lane & 7))*56 + kk*16 + (lane & 8))*2);
                mma_bf16(s[nt], aq[kk], bk);
            }
        }
        // add pl+bias, row max
        float rm0 = -1e30f, rm1 = -1e30f;
        #pragma unroll
        for (int nt = 0; nt < 4; nt++){
            int c = wn*32 + nt*8 + 2*(lane & 3);
            float2 p0 = *(float2*)&pls[r0l*68 + c];
            float2 p1 = *(float2*)&pls[r1l*68 + c];
            s[nt][0] += p0.x; s[nt][1] += p0.y;
            s[nt][2] += p1.x; s[nt][3] += p1.y;
            rm0 = fmaxf(rm0, fmaxf(s[nt][0], s[nt][1]));
            rm1 = fmaxf(rm1, fmaxf(s[nt][2], s[nt][3]));
        }
        rm0 = fmaxf(rm0, __shfl_xor_sync(0xffffffffu, rm0, 1));
        rm0 = fmaxf(rm0, __shfl_xor_sync(0xffffffffu, rm0, 2));
        rm1 = fmaxf(rm1, __shfl_xor_sync(0xffffffffu, rm1, 1));
        rm1 = fmaxf(rm1, __shfl_xor_sync(0xffffffffu, rm1, 2));
        if ((lane & 3) == 0){ redm[wn*64 + r0l] = rm0; redm[wn*64 + r1l] = rm1; }
        __syncthreads();
        float m0 = fmaxf(m0o, fmaxf(redm[r0l], redm[64 + r0l]));
        float m1 = fmaxf(m1o, fmaxf(redm[r1l], redm[64 + r1l]));
        float sc0 = __expf(m0o - m0), sc1 = __expf(m1o - m1);
        m0o = m0; m1o = m1;
        float rs0 = 0.f, rs1 = 0.f;
        #pragma unroll
        for (int nt = 0; nt < 4; nt++){
            int c = wn*32 + nt*8 + 2*(lane & 3);
            float p00 = __expf(s[nt][0] - m0), p01 = __expf(s[nt][1] - m0);
            float p10 = __expf(s[nt][2] - m1), p11 = __expf(s[nt][3] - m1);
            rs0 += p00 + p01; rs1 += p10 + p11;
            *(unsigned*)&Ps[r0l*72 + c] = f2bf2(p00, p01);
            *(unsigned*)&Ps[r1l*72 + c] = f2bf2(p10, p11);
        }
        rs0 += __shfl_xor_sync(0xffffffffu, rs0, 1);
        rs0 += __shfl_xor_sync(0xffffffffu, rs0, 2);
        rs1 += __shfl_xor_sync(0xffffffffu, rs1, 1);
        rs1 += __shfl_xor_sync(0xffffffffu, rs1, 2);
        if ((lane & 3) == 0){ reds[wn*64 + r0l] = rs0; reds[wn*64 + r1l] = rs1; }
        #pragma unroll
        for (int nt = 0; nt < 6; nt++){
            acc[nt][0] *= sc0; acc[nt][1] *= sc0;
            acc[nt][2] *= sc1; acc[nt][3] *= sc1;
        }
        __syncthreads();
        l0 = l0 * sc0 + reds[r0l] + reds[64 + r0l];
        l1 = l1 * sc1 + reds[r1l] + reds[64 + r1l];
        // O += P V  (warp covers kv range wn*32..+32)
        #pragma unroll
        for (int kk = 0; kk < 32; kk += 16){
            unsigned ap[4];
            ldsm4(ap, pB + ((wm*16 + arow)*72 + wn*32 + kk + acol)*2);
            #pragma unroll
            for (int nt = 0; nt < 6; nt++){
                unsigned bv[2];
                ldsm2t(bv, vB + ((wn*32 + kk + (lane & 15))*56 + nt*8)*2);
                mma_bf16(acc[nt], ap, bv);
            }
        }
        __syncthreads();
    }

    // combine the two kv-half partial O's (reuse pls region as f32, stride 52)
    float* Of = pls;
    if (wn == 1){
        #pragma unroll
        for (int nt = 0; nt < 6; nt++){
            int c = nt*8 + 2*(lane & 3);
            *(float2*)&Of[r0l*52 + c] = make_float2(acc[nt][0], acc[nt][1]);
            *(float2*)&Of[r1l*52 + c] = make_float2(acc[nt][2], acc[nt][3]);
        }
    }
    __syncthreads();
    if (wn == 0){
        float inv0 = 1.f / l0, inv1 = 1.f / l1;
        #pragma unroll
        for (int nt = 0; nt < 6; nt++){
            int c = nt*8 + 2*(lane & 3);
            float2 o0 = *(float2*)&Of[r0l*52 + c];
            float2 o1 = *(float2*)&Of[r1l*52 + c];
            long long gidx0 = (long long)(q0 + r0l)*768 + h*48 + c;
            long long gidx1 = (long long)(q0 + r1l)*768 + h*48 + c;
            float2 gt0 = *(const float2*)&gateg[gidx0];
            float2 gt1 = *(const float2*)&gateg[gidx1];
            float2 out0; out0.x = (acc[nt][0] + o0.x) * inv0 * gt0.x;
                         out0.y = (acc[nt][1] + o0.y) * inv0 * gt0.y;
            float2 out1; out1.x = (acc[nt][2] + o1.x) * inv1 * gt1.x;
                         out1.y = (acc[nt][3] + o1.y) * inv1 * gt1.y;
            *(float2*)&og[gidx0] = out0;
            *(float2*)&og[gidx1] = out1;
        }
    }
}

// ---------------- fused pair LN + pl GEMM (bf16 mma, bf16 out) ----------------
__global__ void pair_k(const float* __restrict__ pc, const float* __restrict__ scale,
                       const float* __restrict__ pw)
{
    __shared__ __align__(16) __nv_bfloat16 spch[64*136];  // LN'd pc; later reused as f32 sout[64x68]
    __shared__ __align__(16) __nv_bfloat16 spwh[128*72];  // pw [k][n]
    int nsb = blockIdx.z;
    int t = threadIdx.x, lane = t & 31, w = t >> 5;
    long long row0 = (long long)blockIdx.x * 64;
    int arow = ((lane >> 3) & 1) * 8 + (lane & 7);
    int acol = (lane >> 4) << 3;

    // stage weights [128 k][64 n] -> spwh[k][n]
    for (int i = t; i < 2048; i += 256){
        int kr = i >> 4, n4 = (i & 15) << 2;
        float4 v = *(const float4*)&pw[nsb*8192 + kr*64 + n4];
        uint2 u; u.x = f2bf2(v.x, v.y); u.y = f2bf2(v.z, v.w);
        *(uint2*)&spwh[kr*72 + n4] = u;
    }
    // LN per row, straight from gmem, bf16 out
    float4 sc4 = *(const float4*)&scale[lane*4];
    for (int rr = 0; rr < 8; rr++){
        int r = w*8 + rr;
        float4 xv = *(const float4*)&pc[(row0 + r)*128 + lane*4];
        float s = xv.x + xv.y + xv.z + xv.w;
        #pragma unroll
        for (int o = 16; o; o >>= 1) s += __shfl_xor_sync(0xffffffffu, s, o);
        float m = s * (1.f/128.f);
        float d0 = xv.x - m, d1 = xv.y - m, d2 = xv.z - m, d3 = xv.w - m;
        float vq = d0*d0 + d1*d1 + d2*d2 + d3*d3;
        #pragma unroll
        for (int o = 16; o; o >>= 1) vq += __shfl_xor_sync(0xffffffffu, vq, o);
        float rstd = rsqrtf(vq * (1.f/128.f) + 1e-5f);
        uint2 u;
        u.x = f2bf2(d0*rstd*sc4.x, d1*rstd*sc4.y);
        u.y = f2bf2(d2*rstd*sc4.z, d3*rstd*sc4.w);
        *(uint2*)&spch[r*136 + lane*4] = u;
    }
    __syncthreads();

    int wm = w & 3, wn = w >> 2;
    float acc[4][4];
    #pragma unroll
    for (int i = 0; i < 4; i++)
        #pragma unroll
        for (int q = 0; q < 4; q++) acc[i][q] = 0.f;

    unsigned aB = s2u(spch), bB = s2u(spwh);
    #pragma unroll
    for (int k16 = 0; k16 < 128; k16 += 16){
        unsigned af[4];
        ldsm4(af, aB + ((wm*16 + arow)*136 + k16 + acol)*2);
        #pragma unroll
        for (int nt = 0; nt < 4; nt++){
            unsigned bf2_[2];
            ldsm2t(bf2_, bB + ((k16 + (lane & 15))*72 + wn*32 + nt*8)*2);
            mma_bf16(acc[nt], af, bf2_);
        }
    }
    __syncthreads();

    float* sout = (float*)spch;   // 64 cols x 68 stride
    int r = wm*16 + (lane >> 2);
    #pragma unroll
    for (int nt = 0; nt < 4; nt++){
        int c = wn*32 + nt*8 + 2*(lane & 3);
        sout[(c  )*68 + r    ] = acc[nt][0];
        sout[(c+1)*68 + r    ] = acc[nt][1];
        sout[(c  )*68 + r + 8] = acc[nt][2];
        sout[(c+1)*68 + r + 8] = acc[nt][3];
    }
    __syncthreads();
    for (int i = t; i < 4096; i += 256){
        int col = i >> 6, m = i & 63;
        g_pl[((long long)(nsb*64 + col))*NNSQ_ + row0 + m] = __float2bfloat16(sout[col*68 + m]);
    }
}

// ---------------- small kernels ----------------
__global__ void bias_k(const float* __restrict__ mask){
    int i = blockIdx.x * 256 + threadIdx.x;
    if (i < NN_) g_bias[i] = 1e9f * (mask[i] - 1.f);
}

__global__ void ln384_k(const float* __restrict__ in){
    int r = blockIdx.x, t = threadIdx.x;
    __shared__ float red[32];
    const float* p = in + (long long)r * CS_;
    float v0 = p[t], v1 = p[t+128], v2 = p[t+256];
    float s = blockReduce(v0+v1+v2, red, false);
    float m = s * (1.f/384.f);
    float d0 = v0-m, d1 = v1-m, d2 = v2-m;
    float q = blockReduce(d0*d0+d1*d1+d2*d2, red, false);
    float rstd = rsqrtf(q * (1.f/384.f) + 1e-5f);
    float* o = g_lnsc + (long long)r * CS_;
    o[t] = d0*rstd; o[t+128] = d1*rstd; o[t+256] = d2*rstd;
}

__global__ void cn_k(const float* __restrict__ aln, const float* __restrict__ fln){
    int i = blockIdx.x * 256 + threadIdx.x;
    if (i >= LL_*NN_*CS_) return;
    int l = i / (NN_*CS_);
    int rem = i % (NN_*CS_);
    int c = rem % CS_;
    float b = g_lnsc[rem];
    g_cnA[i] = b * aln[l*CS_ + c];
    g_cnF[i] = b * fln[l*CS_ + c];
}

__global__ void modulate_k(const float* __restrict__ a, const float* __restrict__ sig,
                           const float* __restrict__ add, float* __restrict__ xo){
    int r = blockIdx.x, t = threadIdx.x;
    __shared__ float red[32];
    const float* ar = a + (long long)r * 768;
    float v0 = ar[t], v1 = ar[t+256], v2 = ar[t+512];
    float s = blockReduce(v0+v1+v2, red, false);
    float m = s * (1.f/768.f);
    float d0 = v0-m, d1 = v1-m, d2 = v2-m;
    float q = blockReduce(d0*d0+d1*d1+d2*d2, red, false);
    float rstd = rsqrtf(q * (1.f/768.f) + 1e-5f);
    long long o = (long long)r * 768;
    xo[o+t]     = sig[o+t]     * (d0*rstd) + add[o+t];
    xo[o+t+256] = sig[o+t+256] * (d1*rstd) + add[o+t+256];
    xo[o+t+512] = sig[o+t+512] * (d2*rstd) + add[o+t+512];
}

__global__ void glu_k(){
    int i = blockIdx.x * 256 + threadIdx.x;
    if (i >= NN_*FF_) return;
    int n = i / FF_, f = i % FF_;
    float u1 = g_u[(long long)n*2*FF_ + f];
    float u2 = g_u[(long long)n*2*FF_ + FF_ + f];
    g_c[i] = (u1 / (1.f + expf(-u1))) * u2;
}

// ---------------- host ----------------
static inline void gemm(int M, int N, int K,
    const float* A, int lda, long long sA,
    const float* B, int ldb, long long sB,
    float* C, int ldc, long long sC,
    int mode, const float* P1, long long sP1, int batch)
{
    dim3 gr(N >> 6, M >> 6, batch);
    gemm_tc<<<gr, 256>>>(K, A, lda, sA, B, ldb, sB, C, ldc, sC, mode, P1, sP1);
}

extern "C" void kernel_launch(void* const* d_in, const int* in_sizes, int n_in,
                              void* d_out, int out_size)
{
    const float* act         = (const float*)d_in[0];
    const float* mask        = (const float*)d_in[1];
    const float* single_cond = (const float*)d_in[2];
    const float* pair_cond   = (const float*)d_in[3];
    const float* attn_cln    = (const float*)d_in[4];
    const float* attn_cs_w   = (const float*)d_in[5];
    const float* attn_cs_b   = (const float*)d_in[6];
    const float* attn_cb_w   = (const float*)d_in[7];
    const float* q_w         = (const float*)d_in[8];
    const float* q_b         = (const float*)d_in[9];
    const float* k_w         = (const float*)d_in[10];
    const float* v_w         = (const float*)d_in[11];
    const float* gate_w      = (const float*)d_in[12];
    const float* gate_b      = (const float*)d_in[13];
    const float* out_w       = (const float*)d_in[14];
    const float* attn_azc_w  = (const float*)d_in[15];
    const float* attn_azc_b  = (const float*)d_in[16];
    const float* ffw_cln     = (const float*)d_in[17];
    const float* ffw_cs_w    = (const float*)d_in[18];
    const float* ffw_cs_b    = (const float*)d_in[19];
    const float* ffw_cb_w    = (const float*)d_in[20];
    const float* t1_w        = (const float*)d_in[21];
    const float* t2_w        = (const float*)d_in[22];
    const float* ffw_azc_w   = (const float*)d_in[23];
    const float* ffw_azc_b   = (const float*)d_in[24];
    const float* pair_lns    = (const float*)d_in[25];
    const float* pair_w      = (const float*)d_in[26];
    float* a = (float*)d_out;

    __nv_bfloat16* pl;
    float *x, *qb, *kb, *vb, *gb, *wab, *ub, *cbb;
    float *cnA, *cnF, *sigA, *addA, *azcA, *sigF, *addF, *azcF;
    cudaGetSymbolAddress((void**)&pl,   g_pl);
    cudaGetSymbolAddress((void**)&x,    g_x);
    cudaGetSymbolAddress((void**)&qb,   g_q);
    cudaGetSymbolAddress((void**)&kb,   g_k);
    cudaGetSymbolAddress((void**)&vb,   g_v);
    cudaGetSymbolAddress((void**)&gb,   g_gate);
    cudaGetSymbolAddress((void**)&wab,  g_wa);
    cudaGetSymbolAddress((void**)&ub,   g_u);
    cudaGetSymbolAddress((void**)&cbb,  g_c);
    cudaGetSymbolAddress((void**)&cnA,  g_cnA);
    cudaGetSymbolAddress((void**)&cnF,  g_cnF);
    cudaGetSymbolAddress((void**)&sigA, g_sigA);
    cudaGetSymbolAddress((void**)&addA, g_addA);
    cudaGetSymbolAddress((void**)&azcA, g_azcA);
    cudaGetSymbolAddress((void**)&sigF, g_sigF);
    cudaGetSymbolAddress((void**)&addF, g_addF);
    cudaGetSymbolAddress((void**)&azcF, g_azcF);

    cudaMemcpyAsync(a, act, (size_t)NC_ * sizeof(float), cudaMemcpyDeviceToDevice);

    bias_k<<<3, 256>>>(mask);
    ln384_k<<<NN_, 128>>>(single_cond);
    cn_k<<<(LL_*NN_*CS_ + 255)/256, 256>>>(attn_cln, ffw_cln);

    pair_k<<<dim3(9216, 1, 2), 256>>>(pair_cond, pair_lns, pair_w);

    long long sNCS = (long long)NN_ * CS_;
    long long sWc  = (long long)CS_ * CC_;
    long long sNC  = (long long)NC_;
    gemm(768, 768, 384, cnA, 384, sNCS, attn_cs_w, 768, sWc, sigA, 768, sNC, 2, attn_cs_b, 768, 8);
    gemm(768, 768, 384, cnA, 384, sNCS, attn_cb_w, 768, sWc, addA, 768, sNC, 0, 0, 0, 8);
    gemm(768, 768, 384, single_cond, 384, 0, attn_azc_w, 768, sWc, azcA, 768, sNC, 2, attn_azc_b, 768, 8);
    gemm(768, 768, 384, cnF, 384, sNCS, ffw_cs_w, 768, sWc, sigF, 768, sNC, 2, ffw_cs_b, 768, 8);
    gemm(768, 768, 384, cnF, 384, sNCS, ffw_cb_w, 768, sWc, addF, 768, sNC, 0, 0, 0, 8);
    gemm(768, 768, 384, single_cond, 384, 0, ffw_azc_w, 768, sWc, azcF, 768, sNC, 2, ffw_azc_b, 768, 8);

    cudaFuncSetAttribute(flash_k, cudaFuncAttributeMaxDynamicSharedMemorySize, 49152);

    for (int l = 0; l < 8; l++){
        long long oNC = (long long)l * NC_;
        modulate_k<<<768, 256>>>(a, sigA + oNC, addA + oNC, x);
        qkvg_tc<<<dim3(12, 12, 4), 256>>>(x,
            q_w + oNC, k_w + oNC, v_w + oNC, gate_w + oNC,
            qb, kb, vb, gb, q_b + l*768, gate_b + l*768);
        flash_k<<<dim3(16, 12), 256, 49152>>>(qb, kb, vb, gb,
            pl + (long long)l * HH_ * NNSQ_, wab);
        gemm(768, 768, 768, wab, 768, 0, out_w + oNC, 768, 0, a, 768, 0, 4, azcA + oNC, 0, 1);
        modulate_k<<<768, 256>>>(a, sigF + oNC, addF + oNC, x);
        gemm(768, 3072, 768, x, 768, 0, t1_w + (long long)l*768*3072, 3072, 0, ub, 3072, 0, 0, 0, 0, 1);
        glu_k<<<(NN_*FF_ + 255)/256, 256>>>();
        gemm(768, 768, 1536, cbb, 1536, 0, t2_w + (long long)l*1536*768, 768, 0, a, 768, 0, 4, azcF + oNC, 0, 1);
    }
    (void)in_sizes; (void)n_in; (void)out_size;
}